// round 3
// baseline (speedup 1.0000x reference)
#include <cuda_runtime.h>

#define NN 100000
#define NE 1200000
#define NR 4
#define NL 3
#define DIMN 64
#define NG 128
#define BN_EPS 1e-5f

// ---------------- scratch (static device globals; no allocation) ----------------
__device__ float g_xA[(size_t)NN * DIMN];
__device__ float g_xB[(size_t)NN * DIMN];
__device__ float g_xnew[(size_t)NN * DIMN];
__device__ float g_agg[(size_t)NR * NN * DIMN];   // also holds z (pre-BN) after gemm1
__device__ float g_stats[2 * NR * DIMN];          // [sum | sumsq]
__device__ float g_scale[NR * DIMN];
__device__ float g_shift[NR * DIMN];
__device__ float g_cnt[NG];

__device__ __forceinline__ const float* sel_x(const float* p, int sel) {
    return sel == 1 ? g_xA : (sel == 2 ? g_xB : p);
}

__device__ __forceinline__ void red_add_v4(float* p, float4 v) {
    asm volatile("red.global.add.v4.f32 [%0], {%1, %2, %3, %4};"
                 :: "l"(p), "f"(v.x), "f"(v.y), "f"(v.z), "f"(v.w) : "memory");
}

// ---------------- zeroing ----------------
__global__ void zero_agg_stats_kernel() {
    size_t i = (size_t)blockIdx.x * blockDim.x + threadIdx.x;
    float4 z = make_float4(0.f, 0.f, 0.f, 0.f);
    if (i < (size_t)NR * NN * DIMN / 4) ((float4*)g_agg)[i] = z;
    if (i < 2 * NR * DIMN) g_stats[i] = 0.f;
}

__global__ void zero_out_kernel(float* out) {
    int i = blockIdx.x * blockDim.x + threadIdx.x;
    if (i < NG * DIMN) out[i] = 0.f;
    if (i < NG) g_cnt[i] = 0.f;
}

// ---------------- scatter: agg[r][dst] += x[src] ----------------
__global__ void scatter_kernel(const float* __restrict__ xp,
                               const int* __restrict__ ei,
                               const int* __restrict__ et,
                               int xsel) {
    const float* x = sel_x(xp, xsel);
    int t = blockIdx.x * blockDim.x + threadIdx.x;
    int e = t >> 4;
    if (e >= NE) return;
    int lane = t & 15;
    int s = ei[e];
    int d = ei[NE + e];
    int r = et[e];
    float4 v = *(const float4*)(x + (size_t)s * DIMN + lane * 4);
    float* p = g_agg + ((size_t)r * NN + (size_t)d) * DIMN + lane * 4;
    red_add_v4(p, v);
}

// ---------------- gemm1: m=0 -> xnew = x@Wsl+bsl ; m>=1 -> z = (x+agg)@W1+b1 + BN stats ----------------
__global__ void __launch_bounds__(128) gemm1_kernel(
    const float* __restrict__ xp, int xsel,
    const float* __restrict__ Wsl_l, const float* __restrict__ bsl_l,
    const float* __restrict__ W1_l,  const float* __restrict__ b1_l) {
    const float* xin = sel_x(xp, xsel);
    const int tid = threadIdx.x;
    const int m = blockIdx.y;            // 0 = self-loop, 1..4 = relations
    const int row0 = blockIdx.x * 64;

    __shared__ float Ws[DIMN][DIMN];
    __shared__ float Hs[DIMN][68];       // transposed: Hs[k][row]; 68 floats = 272 B (16B aligned)

    const float* W = (m == 0) ? Wsl_l : (W1_l + (size_t)(m - 1) * DIMN * DIMN);
    for (int i = tid; i < DIMN * DIMN / 4; i += 128)
        ((float4*)Ws)[i] = ((const float4*)W)[i];

    for (int i = tid; i < DIMN * 16; i += 128) {
        int r = i >> 4, c4 = i & 15;
        int row = row0 + r;
        float4 v = make_float4(0.f, 0.f, 0.f, 0.f);
        if (row < NN) {
            v = *(const float4*)(xin + (size_t)row * DIMN + c4 * 4);
            if (m > 0) {
                float4 a = *(const float4*)(g_agg + ((size_t)(m - 1) * NN + row) * DIMN + c4 * 4);
                v.x += a.x; v.y += a.y; v.z += a.z; v.w += a.w;
            }
        }
        int c = c4 * 4;
        Hs[c][r] = v.x; Hs[c + 1][r] = v.y; Hs[c + 2][r] = v.z; Hs[c + 3][r] = v.w;
    }
    __syncthreads();

    const int rg = tid & 15, cg = tid >> 4;   // 16 rowgroups x 8 colgroups
    float acc[4][8];
#pragma unroll
    for (int i = 0; i < 4; i++)
#pragma unroll
        for (int j = 0; j < 8; j++) acc[i][j] = 0.f;

#pragma unroll 8
    for (int k = 0; k < DIMN; k++) {
        float4 a  = *(const float4*)&Hs[k][rg * 4];
        float4 b0 = *(const float4*)&Ws[k][cg * 8];
        float4 b1 = *(const float4*)&Ws[k][cg * 8 + 4];
        float av[4] = {a.x, a.y, a.z, a.w};
        float bv[8] = {b0.x, b0.y, b0.z, b0.w, b1.x, b1.y, b1.z, b1.w};
#pragma unroll
        for (int i = 0; i < 4; i++)
#pragma unroll
            for (int j = 0; j < 8; j++) acc[i][j] += av[i] * bv[j];
    }

    const float* bias = (m == 0) ? bsl_l : (b1_l + (m - 1) * DIMN);
    float* out = (m == 0) ? g_xnew : (g_agg + (size_t)(m - 1) * NN * DIMN);
    float bv[8];
#pragma unroll
    for (int j = 0; j < 8; j++) bv[j] = bias[cg * 8 + j];

    float s[8], q[8];
#pragma unroll
    for (int j = 0; j < 8; j++) { s[j] = 0.f; q[j] = 0.f; }

#pragma unroll
    for (int i = 0; i < 4; i++) {
        int row = row0 + rg * 4 + i;
        if (row < NN) {
            float v[8];
#pragma unroll
            for (int j = 0; j < 8; j++) v[j] = acc[i][j] + bv[j];
            *(float4*)(out + (size_t)row * DIMN + cg * 8)     = make_float4(v[0], v[1], v[2], v[3]);
            *(float4*)(out + (size_t)row * DIMN + cg * 8 + 4) = make_float4(v[4], v[5], v[6], v[7]);
            if (m > 0) {
#pragma unroll
                for (int j = 0; j < 8; j++) { s[j] += v[j]; q[j] += v[j] * v[j]; }
            }
        }
    }

    if (m > 0) {
#pragma unroll
        for (int off = 8; off > 0; off >>= 1) {
#pragma unroll
            for (int j = 0; j < 8; j++) {
                s[j] += __shfl_down_sync(0xffffffffu, s[j], off, 16);
                q[j] += __shfl_down_sync(0xffffffffu, q[j], off, 16);
            }
        }
        if (rg == 0) {
#pragma unroll
            for (int j = 0; j < 8; j++) {
                atomicAdd(&g_stats[(m - 1) * DIMN + cg * 8 + j], s[j]);
                atomicAdd(&g_stats[NR * DIMN + (m - 1) * DIMN + cg * 8 + j], q[j]);
            }
        }
    }
}

// ---------------- BN finalize: scale/shift from stats ----------------
__global__ void bn_finalize_kernel(const float* __restrict__ gamma_l,
                                   const float* __restrict__ beta_l) {
    int i = threadIdx.x;   // 0..255
    float inv_n = 1.0f / (float)NN;
    float mean = g_stats[i] * inv_n;
    float var  = g_stats[NR * DIMN + i] * inv_n - mean * mean;
    float sc   = gamma_l[i] * rsqrtf(var + BN_EPS);
    g_scale[i] = sc;
    g_shift[i] = beta_l[i] - mean * sc;
}

// ---------------- gemm2: xout = relu?( xnew + sum_r relu(z_r*sc+sh) @ W2_r + b2_r ) ----------------
__global__ void __launch_bounds__(128) gemm2_kernel(
    const float* __restrict__ W2_l, const float* __restrict__ b2_l,
    int outsel, int do_relu) {
    float* xout = (outsel == 1) ? g_xA : g_xB;
    const int tid = threadIdx.x;
    const int row0 = blockIdx.x * 64;

    __shared__ float Ws[DIMN][DIMN];
    __shared__ float Hs[DIMN][68];
    __shared__ float ssc[DIMN], ssh[DIMN];

    const int rg = tid & 15, cg = tid >> 4;
    float acc[4][8];
#pragma unroll
    for (int i = 0; i < 4; i++) {
        int row = row0 + rg * 4 + i;
        if (row < NN) {
            float4 u0 = *(const float4*)(g_xnew + (size_t)row * DIMN + cg * 8);
            float4 u1 = *(const float4*)(g_xnew + (size_t)row * DIMN + cg * 8 + 4);
            acc[i][0] = u0.x; acc[i][1] = u0.y; acc[i][2] = u0.z; acc[i][3] = u0.w;
            acc[i][4] = u1.x; acc[i][5] = u1.y; acc[i][6] = u1.z; acc[i][7] = u1.w;
        } else {
#pragma unroll
            for (int j = 0; j < 8; j++) acc[i][j] = 0.f;
        }
    }

    for (int r = 0; r < NR; r++) {
        __syncthreads();
        for (int i = tid; i < DIMN * DIMN / 4; i += 128)
            ((float4*)Ws)[i] = ((const float4*)(W2_l + (size_t)r * DIMN * DIMN))[i];
        if (tid < DIMN) { ssc[tid] = g_scale[r * DIMN + tid]; ssh[tid] = g_shift[r * DIMN + tid]; }
        __syncthreads();

        for (int i = tid; i < DIMN * 16; i += 128) {
            int rr = i >> 4, c4 = i & 15;
            int row = row0 + rr;
            float4 v = make_float4(0.f, 0.f, 0.f, 0.f);
            if (row < NN)
                v = *(const float4*)(g_agg + ((size_t)r * NN + row) * DIMN + c4 * 4);
            int c = c4 * 4;
            Hs[c][rr]     = fmaxf(fmaf(v.x, ssc[c],     ssh[c]),     0.f);
            Hs[c + 1][rr] = fmaxf(fmaf(v.y, ssc[c + 1], ssh[c + 1]), 0.f);
            Hs[c + 2][rr] = fmaxf(fmaf(v.z, ssc[c + 2], ssh[c + 2]), 0.f);
            Hs[c + 3][rr] = fmaxf(fmaf(v.w, ssc[c + 3], ssh[c + 3]), 0.f);
        }
        __syncthreads();

#pragma unroll 8
        for (int k = 0; k < DIMN; k++) {
            float4 a  = *(const float4*)&Hs[k][rg * 4];
            float4 b0 = *(const float4*)&Ws[k][cg * 8];
            float4 b1 = *(const float4*)&Ws[k][cg * 8 + 4];
            float av[4] = {a.x, a.y, a.z, a.w};
            float bv[8] = {b0.x, b0.y, b0.z, b0.w, b1.x, b1.y, b1.z, b1.w};
#pragma unroll
            for (int i = 0; i < 4; i++)
#pragma unroll
                for (int j = 0; j < 8; j++) acc[i][j] += av[i] * bv[j];
        }
    }

    float bv[8];
#pragma unroll
    for (int j = 0; j < 8; j++) {
        float b = 0.f;
#pragma unroll
        for (int r = 0; r < NR; r++) b += b2_l[r * DIMN + cg * 8 + j];
        bv[j] = b;
    }

#pragma unroll
    for (int i = 0; i < 4; i++) {
        int row = row0 + rg * 4 + i;
        if (row < NN) {
            float v[8];
#pragma unroll
            for (int j = 0; j < 8; j++) {
                v[j] = acc[i][j] + bv[j];
                if (do_relu) v[j] = fmaxf(v[j], 0.f);
            }
            *(float4*)(xout + (size_t)row * DIMN + cg * 8)     = make_float4(v[0], v[1], v[2], v[3]);
            *(float4*)(xout + (size_t)row * DIMN + cg * 8 + 4) = make_float4(v[4], v[5], v[6], v[7]);
        }
    }
}

// ---------------- pooling ----------------
__global__ void pool_kernel(int xsel, const int* __restrict__ batch,
                            float* __restrict__ out) {
    const float* x = sel_x(nullptr, xsel);
    int t = blockIdx.x * blockDim.x + threadIdx.x;
    int node = t >> 4;
    if (node >= NN) return;
    int lane = t & 15;
    int g = batch[node];
    float4 v = *(const float4*)(x + (size_t)node * DIMN + lane * 4);
    red_add_v4(out + g * DIMN + lane * 4, v);
    if (lane == 0) atomicAdd(&g_cnt[g], 1.0f);
}

__global__ void pool_div_kernel(float* out) {
    int i = blockIdx.x * blockDim.x + threadIdx.x;
    if (i < NG * DIMN) out[i] /= fmaxf(g_cnt[i >> 6], 1.0f);
}

// ---------------- driver ----------------
extern "C" void kernel_launch(void* const* d_in, const int* in_sizes, int n_in,
                              void* d_out, int out_size) {
    const float* x     = (const float*)d_in[0];
    const int*   ei    = (const int*)d_in[1];
    const int*   et    = (const int*)d_in[2];
    const int*   batch = (const int*)d_in[3];
    const float* Wsl   = (const float*)d_in[4];
    const float* bsl   = (const float*)d_in[5];
    const float* W1    = (const float*)d_in[6];
    const float* b1    = (const float*)d_in[7];
    const float* gamma = (const float*)d_in[8];
    const float* beta  = (const float*)d_in[9];
    const float* W2    = (const float*)d_in[10];
    const float* b2    = (const float*)d_in[11];
    float* out = (float*)d_out;

    zero_out_kernel<<<(NG * DIMN + 255) / 256, 256>>>(out);

    const int tiles = (NN + 63) / 64;
    const int zeroblocks = (int)(((size_t)NR * NN * DIMN / 4 + 255) / 256);

    int cur = 0;  // 0 = harness input x, 1 = g_xA, 2 = g_xB
    for (int l = 0; l < NL; l++) {
        zero_agg_stats_kernel<<<zeroblocks, 256>>>();
        scatter_kernel<<<(int)(((size_t)NE * 16 + 255) / 256), 256>>>(x, ei, et, cur);
        gemm1_kernel<<<dim3(tiles, 5), 128>>>(
            x, cur,
            Wsl + (size_t)l * DIMN * DIMN, bsl + (size_t)l * DIMN,
            W1 + (size_t)l * NR * DIMN * DIMN, b1 + (size_t)l * NR * DIMN);
        bn_finalize_kernel<<<1, NR * DIMN>>>(gamma + (size_t)l * NR * DIMN,
                                             beta + (size_t)l * NR * DIMN);
        int nxt = (l % 2) ? 2 : 1;
        gemm2_kernel<<<tiles, 128>>>(W2 + (size_t)l * NR * DIMN * DIMN,
                                     b2 + (size_t)l * NR * DIMN,
                                     nxt, (l < NL - 1) ? 1 : 0);
        cur = nxt;
    }

    pool_kernel<<<(int)(((size_t)NN * 16 + 255) / 256), 256>>>(cur, batch, out);
    pool_div_kernel<<<(NG * DIMN + 255) / 256, 256>>>(out);
}

// round 6
// speedup vs baseline: 1.6337x; 1.6337x over previous
#include <cuda_runtime.h>
#include <cuda_bf16.h>
#include <stdint.h>

#define NN 100000
#define NE 1200000
#define NR 4
#define NL 3
#define DIMN 64
#define NG 128
#define BN_EPS 1e-5f
#define TILES1 ((NN + 127) / 128)   // 782 row tiles of 128

// ---------------- scratch (static device globals; no allocation) ----------------
__device__ float g_xA[(size_t)NN * DIMN];
__device__ float g_xB[(size_t)NN * DIMN];
__device__ float g_xnew[(size_t)NN * DIMN];
__device__ float g_agg[(size_t)NR * NN * DIMN];   // agg, then z (pre-BN) after gemm1
__device__ float g_stats[2 * NR * DIMN];          // [sum | sumsq]
__device__ float g_scale[NR * DIMN];
__device__ float g_shift[NR * DIMN];
__device__ float g_cnt[NG];
// transposed + bf16-split weights: [layer][mat 0..8][n][k]; mat 0=Wsl, 1..4=W1, 5..8=W2
__device__ __align__(16) __nv_bfloat16 g_wbh[(size_t)NL * 9 * DIMN * DIMN];
__device__ __align__(16) __nv_bfloat16 g_wbl[(size_t)NL * 9 * DIMN * DIMN];

// smem layout (bytes): A rows 144B pitch (72 halves), B rows 144B pitch
#define AH_OFF 0
#define AL_OFF 18432
#define BH_OFF 36864
#define BL_OFF 46080
#define ST_OFF 55296
#define SMEM_SZ 55808

// ---------------- helpers ----------------
__device__ __forceinline__ uint32_t smem_u32(const void* p) {
    uint32_t a;
    asm("{ .reg .u64 t; cvta.to.shared.u64 t, %1; cvt.u32.u64 %0, t; }" : "=r"(a) : "l"(p));
    return a;
}
__device__ __forceinline__ void red_add_v4(float* p, float4 v) {
    asm volatile("red.global.add.v4.f32 [%0], {%1, %2, %3, %4};"
                 :: "l"(p), "f"(v.x), "f"(v.y), "f"(v.z), "f"(v.w) : "memory");
}
__device__ __forceinline__ void ldm_x4(uint32_t* r, uint32_t addr) {
    asm volatile("ldmatrix.sync.aligned.m8n8.x4.shared.b16 {%0,%1,%2,%3}, [%4];"
                 : "=r"(r[0]), "=r"(r[1]), "=r"(r[2]), "=r"(r[3]) : "r"(addr));
}
__device__ __forceinline__ void mma_bf16(float* c, const uint32_t* a, const uint32_t* b) {
    asm volatile("mma.sync.aligned.m16n8k16.row.col.f32.bf16.bf16.f32 "
                 "{%0,%1,%2,%3}, {%4,%5,%6,%7}, {%8,%9}, {%0,%1,%2,%3};"
                 : "+f"(c[0]), "+f"(c[1]), "+f"(c[2]), "+f"(c[3])
                 : "r"(a[0]), "r"(a[1]), "r"(a[2]), "r"(a[3]), "r"(b[0]), "r"(b[1]));
}
// split two fp32 into bf16 hi (packed) + bf16 lo (packed)
__device__ __forceinline__ uint32_t split2(float a, float b, uint32_t& lo_out) {
    __nv_bfloat16 ha = __float2bfloat16_rn(a), hb = __float2bfloat16_rn(b);
    float ra = a - __bfloat162float(ha), rb = b - __bfloat162float(hb);
    __nv_bfloat16 la = __float2bfloat16_rn(ra), lb = __float2bfloat16_rn(rb);
    lo_out = (uint32_t)__bfloat16_as_ushort(la) | ((uint32_t)__bfloat16_as_ushort(lb) << 16);
    return (uint32_t)__bfloat16_as_ushort(ha) | ((uint32_t)__bfloat16_as_ushort(hb) << 16);
}
__device__ __forceinline__ const float* sel_x(const float* p, int sel) {
    return sel == 1 ? g_xA : (sel == 2 ? g_xB : p);
}

// ---------------- weight prep: transpose + bf16 hi/lo split ----------------
__global__ void prep_w_kernel(const float* __restrict__ Wsl, const float* __restrict__ W1,
                              const float* __restrict__ W2) {
    int b = blockIdx.x;              // 0..26 : l*9 + mat
    int l = b / 9, mm = b % 9;
    const float* src;
    if (mm == 0)      src = Wsl + (size_t)l * DIMN * DIMN;
    else if (mm <= 4) src = W1 + ((size_t)l * NR + (mm - 1)) * DIMN * DIMN;
    else              src = W2 + ((size_t)l * NR + (mm - 5)) * DIMN * DIMN;
    __nv_bfloat16* dh = g_wbh + (size_t)b * DIMN * DIMN;
    __nv_bfloat16* dl = g_wbl + (size_t)b * DIMN * DIMN;
    for (int i = threadIdx.x; i < DIMN * DIMN; i += blockDim.x) {
        int k = i >> 6, n = i & 63;
        float v = src[i];
        __nv_bfloat16 h = __float2bfloat16_rn(v);
        __nv_bfloat16 lo = __float2bfloat16_rn(v - __bfloat162float(h));
        dh[n * DIMN + k] = h;      // transposed: [n][k]
        dl[n * DIMN + k] = lo;
    }
}

// ---------------- zeroing ----------------
__global__ void zero_agg_stats_kernel() {
    size_t i = (size_t)blockIdx.x * blockDim.x + threadIdx.x;
    if (i < (size_t)NR * NN * DIMN / 4)
        ((float4*)g_agg)[i] = make_float4(0.f, 0.f, 0.f, 0.f);
    if (i < 2 * NR * DIMN) g_stats[i] = 0.f;
}
__global__ void zero_out_kernel(float* out) {
    int i = blockIdx.x * blockDim.x + threadIdx.x;
    if (i < NG * DIMN) out[i] = 0.f;
    if (i < NG) g_cnt[i] = 0.f;
}

// ---------------- scatter: agg[r][dst] += x[src] ----------------
__global__ void scatter_kernel(const float* __restrict__ xp, const int* __restrict__ ei,
                               const int* __restrict__ et, int xsel) {
    const float* x = sel_x(xp, xsel);
    int t = blockIdx.x * blockDim.x + threadIdx.x;
    int e = t >> 4;
    if (e >= NE) return;
    int lane = t & 15;
    int s = ei[e], d = ei[NE + e], r = et[e];
    float4 v = *(const float4*)(x + (size_t)s * DIMN + lane * 4);
    red_add_v4(g_agg + ((size_t)r * NN + (size_t)d) * DIMN + lane * 4, v);
}

// ---------------- shared GEMM core: mma over staged smem, acc += A*B (3-pass bf16) ----------------
__device__ __forceinline__ void mma_tile(uint32_t sb, int rowbase, int colbase, int lane,
                                         float acc[2][4][4]) {
    uint32_t aoff = (uint32_t)((lane & 15) * 144 + ((lane >> 4) << 4));
    uint32_t boff = (uint32_t)(((lane & 7) + ((lane >> 4) << 3)) * 144 + (((lane >> 3) & 1) << 4));
#pragma unroll
    for (int k = 0; k < 4; k++) {
        uint32_t kb = k * 32;
        uint32_t ah0[4], ah1[4], bh0[4], bh1[4], al0[4], al1[4], bl0[4], bl1[4];
        ldm_x4(ah0, sb + AH_OFF + rowbase * 144 + aoff + kb);
        ldm_x4(ah1, sb + AH_OFF + (rowbase + 16) * 144 + aoff + kb);
        ldm_x4(bh0, sb + BH_OFF + colbase * 144 + boff + kb);
        ldm_x4(bh1, sb + BH_OFF + (colbase + 16) * 144 + boff + kb);
        ldm_x4(al0, sb + AL_OFF + rowbase * 144 + aoff + kb);
        ldm_x4(al1, sb + AL_OFF + (rowbase + 16) * 144 + aoff + kb);
        ldm_x4(bl0, sb + BL_OFF + colbase * 144 + boff + kb);
        ldm_x4(bl1, sb + BL_OFF + (colbase + 16) * 144 + boff + kb);
#pragma unroll
        for (int nt = 0; nt < 4; nt++) {
            uint32_t* bh = (nt < 2 ? bh0 : bh1) + (nt & 1) * 2;
            uint32_t* bl = (nt < 2 ? bl0 : bl1) + (nt & 1) * 2;
            mma_bf16(acc[0][nt], ah0, bh);
            mma_bf16(acc[1][nt], ah1, bh);
            mma_bf16(acc[0][nt], ah0, bl);
            mma_bf16(acc[1][nt], ah1, bl);
            mma_bf16(acc[0][nt], al0, bh);
            mma_bf16(acc[1][nt], al1, bh);
        }
    }
}
__device__ __forceinline__ void stage_B(char* smem, int tid, int mat) {
    const char* gh = (const char*)g_wbh + (size_t)mat * 8192;
    const char* gl = (const char*)g_wbl + (size_t)mat * 8192;
    for (int i = tid; i < 64 * 8; i += 256) {
        int n = i >> 3, ch = i & 7;
        *(uint4*)(smem + BH_OFF + n * 144 + ch * 16) = *(const uint4*)(gh + n * 128 + ch * 16);
        *(uint4*)(smem + BL_OFF + n * 144 + ch * 16) = *(const uint4*)(gl + n * 128 + ch * 16);
    }
}
__device__ __forceinline__ void store_D(char* smem, int lane, int w, float acc[2][4][4]) {
    float* Ds = (float*)smem;
    int rowbase = (w & 3) * 32, colbase = (w >> 2) * 32;
    int g = lane >> 2, c2 = (lane & 3) * 2;
#pragma unroll
    for (int mt = 0; mt < 2; mt++)
#pragma unroll
        for (int nt = 0; nt < 4; nt++) {
            int row = rowbase + mt * 16 + g;
            int col = colbase + nt * 8 + c2;
            *(float2*)(Ds + row * 68 + col)       = make_float2(acc[mt][nt][0], acc[mt][nt][1]);
            *(float2*)(Ds + (row + 8) * 68 + col) = make_float2(acc[mt][nt][2], acc[mt][nt][3]);
        }
}

// ---------------- gemm1: m=0 -> xnew = x@Wsl+bsl ; m>=1 -> z = (x+agg)@W1 (+BN stats) ----------------
__global__ void __launch_bounds__(256) gemm1_tc(const float* __restrict__ xp, int xsel,
                                                int layer, const float* __restrict__ bsl_l) {
    extern __shared__ char smem[];
    uint32_t sb = smem_u32(smem);
    const float* xin = sel_x(xp, xsel);
    const int tid = threadIdx.x, w = tid >> 5, lane = tid & 31;
    const int m = blockIdx.y;
    const int row0 = blockIdx.x * 128;
    const int kg = tid & 15;

    float* sstat = (float*)(smem + ST_OFF);
    if (tid < 128) sstat[tid] = 0.f;

    stage_B(smem, tid, layer * 9 + m);

    const float* ag = g_agg + (size_t)(m - 1) * NN * DIMN;
    for (int i = tid; i < 128 * 16; i += 256) {
        int rr = i >> 4;
        int row = row0 + rr;
        float4 v = make_float4(0.f, 0.f, 0.f, 0.f);
        if (row < NN) {
            v = *(const float4*)(xin + (size_t)row * DIMN + kg * 4);
            if (m > 0) {
                float4 a = *(const float4*)(ag + (size_t)row * DIMN + kg * 4);
                v.x += a.x; v.y += a.y; v.z += a.z; v.w += a.w;
            }
        }
        uint32_t l01, l23;
        uint32_t h01 = split2(v.x, v.y, l01), h23 = split2(v.z, v.w, l23);
        *(uint2*)(smem + AH_OFF + rr * 144 + kg * 8) = make_uint2(h01, h23);
        *(uint2*)(smem + AL_OFF + rr * 144 + kg * 8) = make_uint2(l01, l23);
    }
    __syncthreads();

    float acc[2][4][4];
#pragma unroll
    for (int a = 0; a < 2; a++)
#pragma unroll
        for (int b = 0; b < 4; b++)
#pragma unroll
            for (int c = 0; c < 4; c++) acc[a][b][c] = 0.f;

    mma_tile(sb, (w & 3) * 32, (w >> 2) * 32, lane, acc);

    __syncthreads();
    store_D(smem, lane, w, acc);
    __syncthreads();

    float* Ds = (float*)smem;
    float4 bias = make_float4(0.f, 0.f, 0.f, 0.f);
    if (m == 0) bias = *(const float4*)(bsl_l + kg * 4);
    float* outbase = (m == 0) ? g_xnew : (g_agg + (size_t)(m - 1) * NN * DIMN);
    float s[4] = {0.f, 0.f, 0.f, 0.f}, q[4] = {0.f, 0.f, 0.f, 0.f};
#pragma unroll
    for (int j = 0; j < 8; j++) {
        int rr = (tid >> 4) + j * 16;
        int row = row0 + rr;
        if (row < NN) {
            float4 v = *(float4*)(Ds + rr * 68 + kg * 4);
            if (m == 0) { v.x += bias.x; v.y += bias.y; v.z += bias.z; v.w += bias.w; }
            *(float4*)(outbase + (size_t)row * DIMN + kg * 4) = v;
            if (m > 0) {
                s[0] += v.x; s[1] += v.y; s[2] += v.z; s[3] += v.w;
                q[0] += v.x * v.x; q[1] += v.y * v.y; q[2] += v.z * v.z; q[3] += v.w * v.w;
            }
        }
    }
    if (m > 0) {
#pragma unroll
        for (int c = 0; c < 4; c++) {
            atomicAdd(&sstat[kg * 4 + c], s[c]);
            atomicAdd(&sstat[64 + kg * 4 + c], q[c]);
        }
        __syncthreads();
        if (tid < 64) {
            atomicAdd(&g_stats[(m - 1) * DIMN + tid], sstat[tid]);
            atomicAdd(&g_stats[NR * DIMN + (m - 1) * DIMN + tid], sstat[64 + tid]);
        }
    }
}

// ---------------- BN finalize ----------------
__global__ void bn_finalize_kernel(const float* __restrict__ gamma_l,
                                   const float* __restrict__ beta_l) {
    int i = threadIdx.x;   // 0..255
    float inv_n = 1.0f / (float)NN;
    float mean = g_stats[i] * inv_n;
    float var  = g_stats[NR * DIMN + i] * inv_n - mean * mean;
    float sc   = gamma_l[i] * rsqrtf(var + BN_EPS);
    g_scale[i] = sc;
    g_shift[i] = beta_l[i] - mean * sc;
}

// ---------------- gemm2: xout = relu?( xnew + sum_r relu(z_r*sc+sh)@W2_r + sum_r b2_r ) ----------------
__global__ void __launch_bounds__(256) gemm2_tc(int outsel, int do_relu, int layer,
                                                const float* __restrict__ b2_l) {
    extern __shared__ char smem[];
    uint32_t sb = smem_u32(smem);
    float* xout = (outsel == 1) ? g_xA : g_xB;
    const int tid = threadIdx.x, w = tid >> 5, lane = tid & 31;
    const int row0 = blockIdx.x * 128;
    const int kg = tid & 15;

    float acc[2][4][4];
#pragma unroll
    for (int a = 0; a < 2; a++)
#pragma unroll
        for (int b = 0; b < 4; b++)
#pragma unroll
            for (int c = 0; c < 4; c++) acc[a][b][c] = 0.f;

    for (int r = 0; r < NR; r++) {
        __syncthreads();
        stage_B(smem, tid, layer * 9 + 5 + r);
        const float* z = g_agg + (size_t)r * NN * DIMN;
        float4 sc = *(const float4*)(g_scale + r * DIMN + kg * 4);
        float4 sh = *(const float4*)(g_shift + r * DIMN + kg * 4);
        for (int i = tid; i < 128 * 16; i += 256) {
            int rr = i >> 4;
            int row = row0 + rr;
            float4 v = make_float4(0.f, 0.f, 0.f, 0.f);
            if (row < NN) {
                float4 zz = *(const float4*)(z + (size_t)row * DIMN + kg * 4);
                v.x = fmaxf(fmaf(zz.x, sc.x, sh.x), 0.f);
                v.y = fmaxf(fmaf(zz.y, sc.y, sh.y), 0.f);
                v.z = fmaxf(fmaf(zz.z, sc.z, sh.z), 0.f);
                v.w = fmaxf(fmaf(zz.w, sc.w, sh.w), 0.f);
            }
            uint32_t l01, l23;
            uint32_t h01 = split2(v.x, v.y, l01), h23 = split2(v.z, v.w, l23);
            *(uint2*)(smem + AH_OFF + rr * 144 + kg * 8) = make_uint2(h01, h23);
            *(uint2*)(smem + AL_OFF + rr * 144 + kg * 8) = make_uint2(l01, l23);
        }
        __syncthreads();
        mma_tile(sb, (w & 3) * 32, (w >> 2) * 32, lane, acc);
    }

    __syncthreads();
    store_D(smem, lane, w, acc);
    __syncthreads();

    float* Ds = (float*)smem;
    float4 b2s = make_float4(0.f, 0.f, 0.f, 0.f);
#pragma unroll
    for (int r = 0; r < NR; r++) {
        float4 b = *(const float4*)(b2_l + r * DIMN + kg * 4);
        b2s.x += b.x; b2s.y += b.y; b2s.z += b.z; b2s.w += b.w;
    }
#pragma unroll
    for (int j = 0; j < 8; j++) {
        int rr = (tid >> 4) + j * 16;
        int row = row0 + rr;
        if (row < NN) {
            float4 v = *(float4*)(Ds + rr * 68 + kg * 4);
            float4 u = *(const float4*)(g_xnew + (size_t)row * DIMN + kg * 4);
            v.x += u.x + b2s.x; v.y += u.y + b2s.y;
            v.z += u.z + b2s.z; v.w += u.w + b2s.w;
            if (do_relu) {
                v.x = fmaxf(v.x, 0.f); v.y = fmaxf(v.y, 0.f);
                v.z = fmaxf(v.z, 0.f); v.w = fmaxf(v.w, 0.f);
            }
            *(float4*)(xout + (size_t)row * DIMN + kg * 4) = v;
        }
    }
}

// ---------------- pooling ----------------
__global__ void pool_kernel(int xsel, const int* __restrict__ batch, float* __restrict__ out) {
    const float* x = sel_x(nullptr, xsel);
    int t = blockIdx.x * blockDim.x + threadIdx.x;
    int node = t >> 4;
    if (node >= NN) return;
    int lane = t & 15;
    int g = batch[node];
    float4 v = *(const float4*)(x + (size_t)node * DIMN + lane * 4);
    red_add_v4(out + g * DIMN + lane * 4, v);
    if (lane == 0) atomicAdd(&g_cnt[g], 1.0f);
}
__global__ void pool_div_kernel(float* out) {
    int i = blockIdx.x * blockDim.x + threadIdx.x;
    if (i < NG * DIMN) out[i] /= fmaxf(g_cnt[i >> 6], 1.0f);
}

// ---------------- driver ----------------
extern "C" void kernel_launch(void* const* d_in, const int* in_sizes, int n_in,
                              void* d_out, int out_size) {
    const float* x     = (const float*)d_in[0];
    const int*   ei    = (const int*)d_in[1];
    const int*   et    = (const int*)d_in[2];
    const int*   batch = (const int*)d_in[3];
    const float* Wsl   = (const float*)d_in[4];
    const float* bsl   = (const float*)d_in[5];
    const float* W1    = (const float*)d_in[6];
    /* b1 cancels under BatchNorm (mean subtraction) — unused */
    const float* gamma = (const float*)d_in[8];
    const float* beta  = (const float*)d_in[9];
    const float* W2    = (const float*)d_in[10];
    const float* b2    = (const float*)d_in[11];
    float* out = (float*)d_out;

    cudaFuncSetAttribute(gemm1_tc, cudaFuncAttributeMaxDynamicSharedMemorySize, SMEM_SZ);
    cudaFuncSetAttribute(gemm2_tc, cudaFuncAttributeMaxDynamicSharedMemorySize, SMEM_SZ);

    prep_w_kernel<<<NL * 9, 256>>>(Wsl, W1, W2);
    zero_out_kernel<<<(NG * DIMN + 255) / 256, 256>>>(out);

    const int zeroblocks = (int)(((size_t)NR * NN * DIMN / 4 + 255) / 256);

    int cur = 0;  // 0 = harness input x, 1 = g_xA, 2 = g_xB
    for (int l = 0; l < NL; l++) {
        zero_agg_stats_kernel<<<zeroblocks, 256>>>();
        scatter_kernel<<<(int)(((size_t)NE * 16 + 255) / 256), 256>>>(x, ei, et, cur);
        gemm1_tc<<<dim3(TILES1, 5), 256, SMEM_SZ>>>(x, cur, l, bsl + (size_t)l * DIMN);
        bn_finalize_kernel<<<1, NR * DIMN>>>(gamma + (size_t)l * NR * DIMN,
                                             beta + (size_t)l * NR * DIMN);
        int nxt = (l % 2) ? 2 : 1;
        gemm2_tc<<<TILES1, 256, SMEM_SZ>>>(nxt, (l < NL - 1) ? 1 : 0, l,
                                           b2 + (size_t)l * NR * DIMN);
        cur = nxt;
    }

    pool_kernel<<<(int)(((size_t)NN * 16 + 255) / 256), 256>>>(cur, batch, out);
    pool_div_kernel<<<(NG * DIMN + 255) / 256, 256>>>(out);
}

// round 7
// speedup vs baseline: 1.7489x; 1.0705x over previous
#include <cuda_runtime.h>
#include <cuda_bf16.h>
#include <stdint.h>

#define NN 100000
#define NE 1200000
#define NR 4
#define NL 3
#define DIMN 64
#define NG 128
#define BN_EPS 1e-5f
#define TILES1 ((NN + 127) / 128)   // 782 row tiles of 128

// ---------------- scratch (static device globals; no allocation) ----------------
__device__ float g_xA[(size_t)NN * DIMN];
__device__ float g_xB[(size_t)NN * DIMN];
__device__ float g_xnew[(size_t)NN * DIMN];
__device__ float g_agg[(size_t)NR * NN * DIMN];   // agg, then z (pre-BN) after gemm1
__device__ float g_stats[2 * NR * DIMN];          // [sum | sumsq]
__device__ float g_scale[NR * DIMN];
__device__ float g_shift[NR * DIMN];
__device__ float g_cnt[NG];
// CSR-by-dst (built once per launch; graph static across layers)
__device__ int g_ecnt[NN];
__device__ int g_ofs[NN + 1];
__device__ int g_curp[NN];
__device__ int g_eidx[NE];        // packed: src | (rel << 17)
// transposed + bf16-split weights: [layer][mat 0..8][n][k]; mat 0=Wsl, 1..4=W1, 5..8=W2
__device__ __align__(16) __nv_bfloat16 g_wbh[(size_t)NL * 9 * DIMN * DIMN];
__device__ __align__(16) __nv_bfloat16 g_wbl[(size_t)NL * 9 * DIMN * DIMN];

// smem layout (bytes): A rows 144B pitch (72 halves), B rows 144B pitch
#define AH_OFF 0
#define AL_OFF 18432
#define BH_OFF 36864
#define BL_OFF 46080
#define ST_OFF 55296
#define SMEM_SZ 55808

// ---------------- helpers ----------------
__device__ __forceinline__ uint32_t smem_u32(const void* p) {
    uint32_t a;
    asm("{ .reg .u64 t; cvta.to.shared.u64 t, %1; cvt.u32.u64 %0, t; }" : "=r"(a) : "l"(p));
    return a;
}
__device__ __forceinline__ void red_add_v4(float* p, float4 v) {
    asm volatile("red.global.add.v4.f32 [%0], {%1, %2, %3, %4};"
                 :: "l"(p), "f"(v.x), "f"(v.y), "f"(v.z), "f"(v.w) : "memory");
}
__device__ __forceinline__ void ldm_x4(uint32_t* r, uint32_t addr) {
    asm volatile("ldmatrix.sync.aligned.m8n8.x4.shared.b16 {%0,%1,%2,%3}, [%4];"
                 : "=r"(r[0]), "=r"(r[1]), "=r"(r[2]), "=r"(r[3]) : "r"(addr));
}
__device__ __forceinline__ void mma_bf16(float* c, const uint32_t* a, const uint32_t* b) {
    asm volatile("mma.sync.aligned.m16n8k16.row.col.f32.bf16.bf16.f32 "
                 "{%0,%1,%2,%3}, {%4,%5,%6,%7}, {%8,%9}, {%0,%1,%2,%3};"
                 : "+f"(c[0]), "+f"(c[1]), "+f"(c[2]), "+f"(c[3])
                 : "r"(a[0]), "r"(a[1]), "r"(a[2]), "r"(a[3]), "r"(b[0]), "r"(b[1]));
}
__device__ __forceinline__ uint32_t split2(float a, float b, uint32_t& lo_out) {
    __nv_bfloat16 ha = __float2bfloat16_rn(a), hb = __float2bfloat16_rn(b);
    float ra = a - __bfloat162float(ha), rb = b - __bfloat162float(hb);
    __nv_bfloat16 la = __float2bfloat16_rn(ra), lb = __float2bfloat16_rn(rb);
    lo_out = (uint32_t)__bfloat16_as_ushort(la) | ((uint32_t)__bfloat16_as_ushort(lb) << 16);
    return (uint32_t)__bfloat16_as_ushort(ha) | ((uint32_t)__bfloat16_as_ushort(hb) << 16);
}
__device__ __forceinline__ const float* sel_x(const float* p, int sel) {
    return sel == 1 ? g_xA : (sel == 2 ? g_xB : p);
}

// ---------------- weight prep: transpose + bf16 hi/lo split ----------------
__global__ void prep_w_kernel(const float* __restrict__ Wsl, const float* __restrict__ W1,
                              const float* __restrict__ W2) {
    int b = blockIdx.x;              // 0..26 : l*9 + mat
    int l = b / 9, mm = b % 9;
    const float* src;
    if (mm == 0)      src = Wsl + (size_t)l * DIMN * DIMN;
    else if (mm <= 4) src = W1 + ((size_t)l * NR + (mm - 1)) * DIMN * DIMN;
    else              src = W2 + ((size_t)l * NR + (mm - 5)) * DIMN * DIMN;
    __nv_bfloat16* dh = g_wbh + (size_t)b * DIMN * DIMN;
    __nv_bfloat16* dl = g_wbl + (size_t)b * DIMN * DIMN;
    for (int i = threadIdx.x; i < DIMN * DIMN; i += blockDim.x) {
        int k = i >> 6, n = i & 63;
        float v = src[i];
        __nv_bfloat16 h = __float2bfloat16_rn(v);
        __nv_bfloat16 lo = __float2bfloat16_rn(v - __bfloat162float(h));
        dh[n * DIMN + k] = h;      // transposed: [n][k]
        dl[n * DIMN + k] = lo;
    }
}

// ---------------- CSR build (once per launch) ----------------
__global__ void zero_cnt_kernel() {
    int i = blockIdx.x * blockDim.x + threadIdx.x;
    if (i < NN) g_ecnt[i] = 0;
}
__global__ void hist_kernel(const int* __restrict__ ei) {
    int e = blockIdx.x * blockDim.x + threadIdx.x;
    if (e < NE) atomicAdd(&g_ecnt[ei[NE + e]], 1);
}
__global__ void scan_kernel() {     // single block, 1024 threads
    __shared__ int wsum[32];
    __shared__ int carry_s;
    int tid = threadIdx.x, lane = tid & 31, wid = tid >> 5;
    if (tid == 0) { carry_s = 0; g_ofs[0] = 0; }
    __syncthreads();
    for (int base = 0; base < NN; base += 1024) {
        int i = base + tid;
        int v = (i < NN) ? g_ecnt[i] : 0;
        int incl = v;
#pragma unroll
        for (int off = 1; off < 32; off <<= 1) {
            int t = __shfl_up_sync(0xffffffffu, incl, off);
            if (lane >= off) incl += t;
        }
        if (lane == 31) wsum[wid] = incl;
        __syncthreads();
        if (wid == 0) {
            int s = wsum[lane];
#pragma unroll
            for (int off = 1; off < 32; off <<= 1) {
                int t = __shfl_up_sync(0xffffffffu, s, off);
                if (lane >= off) s += t;
            }
            wsum[lane] = s;
        }
        __syncthreads();
        int pref = carry_s + (wid ? wsum[wid - 1] : 0);
        int incl_tot = pref + incl;
        if (i < NN) { g_ofs[i + 1] = incl_tot; g_curp[i] = incl_tot - v; }
        __syncthreads();
        if (tid == 0) carry_s += wsum[31];
        __syncthreads();
    }
}
__global__ void fill_kernel(const int* __restrict__ ei, const int* __restrict__ et) {
    int e = blockIdx.x * blockDim.x + threadIdx.x;
    if (e >= NE) return;
    int d = ei[NE + e];
    int pos = atomicAdd(&g_curp[d], 1);
    g_eidx[pos] = ei[e] | (et[e] << 17);
}

// ---------------- gather-reduce: agg[r][node] = sum_{edges(dst=node,rel=r)} x[src] ----------------
__global__ void __launch_bounds__(256) gather_kernel(const float* __restrict__ xp, int xsel) {
    const float* x = sel_x(xp, xsel);
    int t = blockIdx.x * blockDim.x + threadIdx.x;
    int node = t >> 4;
    if (node >= NN) return;
    int lane = t & 15;
    int beg = g_ofs[node], end = g_ofs[node + 1];
    float4 a0 = make_float4(0.f, 0.f, 0.f, 0.f), a1 = a0, a2 = a0, a3 = a0;
    for (int j = beg; j < end; j++) {
        int p = g_eidx[j];
        int s = p & 0x1FFFF, r = p >> 17;
        float4 v = *(const float4*)(x + (size_t)s * DIMN + lane * 4);
        if (r == 0)      { a0.x += v.x; a0.y += v.y; a0.z += v.z; a0.w += v.w; }
        else if (r == 1) { a1.x += v.x; a1.y += v.y; a1.z += v.z; a1.w += v.w; }
        else if (r == 2) { a2.x += v.x; a2.y += v.y; a2.z += v.z; a2.w += v.w; }
        else             { a3.x += v.x; a3.y += v.y; a3.z += v.z; a3.w += v.w; }
    }
    size_t off = (size_t)node * DIMN + lane * 4;
    *(float4*)(g_agg + off)                         = a0;
    *(float4*)(g_agg + (size_t)NN * DIMN + off)     = a1;
    *(float4*)(g_agg + (size_t)2 * NN * DIMN + off) = a2;
    *(float4*)(g_agg + (size_t)3 * NN * DIMN + off) = a3;
}

// ---------------- zeroing ----------------
__global__ void zero_stats_kernel() {
    int i = threadIdx.x;
    if (i < 2 * NR * DIMN) g_stats[i] = 0.f;
}
__global__ void zero_out_kernel(float* out) {
    int i = blockIdx.x * blockDim.x + threadIdx.x;
    if (i < NG * DIMN) out[i] = 0.f;
    if (i < NG) g_cnt[i] = 0.f;
}

// ---------------- shared GEMM core ----------------
__device__ __forceinline__ void mma_tile(uint32_t sb, int rowbase, int colbase, int lane,
                                         float acc[2][4][4]) {
    uint32_t aoff = (uint32_t)((lane & 15) * 144 + ((lane >> 4) << 4));
    uint32_t boff = (uint32_t)(((lane & 7) + ((lane >> 4) << 3)) * 144 + (((lane >> 3) & 1) << 4));
#pragma unroll
    for (int k = 0; k < 4; k++) {
        uint32_t kb = k * 32;
        uint32_t ah0[4], ah1[4], bh0[4], bh1[4], al0[4], al1[4], bl0[4], bl1[4];
        ldm_x4(ah0, sb + AH_OFF + rowbase * 144 + aoff + kb);
        ldm_x4(ah1, sb + AH_OFF + (rowbase + 16) * 144 + aoff + kb);
        ldm_x4(bh0, sb + BH_OFF + colbase * 144 + boff + kb);
        ldm_x4(bh1, sb + BH_OFF + (colbase + 16) * 144 + boff + kb);
        ldm_x4(al0, sb + AL_OFF + rowbase * 144 + aoff + kb);
        ldm_x4(al1, sb + AL_OFF + (rowbase + 16) * 144 + aoff + kb);
        ldm_x4(bl0, sb + BL_OFF + colbase * 144 + boff + kb);
        ldm_x4(bl1, sb + BL_OFF + (colbase + 16) * 144 + boff + kb);
#pragma unroll
        for (int nt = 0; nt < 4; nt++) {
            uint32_t* bh = (nt < 2 ? bh0 : bh1) + (nt & 1) * 2;
            uint32_t* bl = (nt < 2 ? bl0 : bl1) + (nt & 1) * 2;
            mma_bf16(acc[0][nt], ah0, bh);
            mma_bf16(acc[1][nt], ah1, bh);
            mma_bf16(acc[0][nt], ah0, bl);
            mma_bf16(acc[1][nt], ah1, bl);
            mma_bf16(acc[0][nt], al0, bh);
            mma_bf16(acc[1][nt], al1, bh);
        }
    }
}
__device__ __forceinline__ void stage_B(char* smem, int tid, int mat) {
    const char* gh = (const char*)g_wbh + (size_t)mat * 8192;
    const char* gl = (const char*)g_wbl + (size_t)mat * 8192;
    for (int i = tid; i < 64 * 8; i += 256) {
        int n = i >> 3, ch = i & 7;
        *(uint4*)(smem + BH_OFF + n * 144 + ch * 16) = *(const uint4*)(gh + n * 128 + ch * 16);
        *(uint4*)(smem + BL_OFF + n * 144 + ch * 16) = *(const uint4*)(gl + n * 128 + ch * 16);
    }
}
__device__ __forceinline__ void store_D(char* smem, int lane, int w, float acc[2][4][4]) {
    float* Ds = (float*)smem;
    int rowbase = (w & 3) * 32, colbase = (w >> 2) * 32;
    int g = lane >> 2, c2 = (lane & 3) * 2;
#pragma unroll
    for (int mt = 0; mt < 2; mt++)
#pragma unroll
        for (int nt = 0; nt < 4; nt++) {
            int row = rowbase + mt * 16 + g;
            int col = colbase + nt * 8 + c2;
            *(float2*)(Ds + row * 68 + col)       = make_float2(acc[mt][nt][0], acc[mt][nt][1]);
            *(float2*)(Ds + (row + 8) * 68 + col) = make_float2(acc[mt][nt][2], acc[mt][nt][3]);
        }
}

// ---------------- gemm1: m=0 -> xnew = x@Wsl+bsl ; m>=1 -> z = (x+agg)@W1 (+BN stats) ----------------
__global__ void __launch_bounds__(256) gemm1_tc(const float* __restrict__ xp, int xsel,
                                                int layer, const float* __restrict__ bsl_l) {
    extern __shared__ char smem[];
    uint32_t sb = smem_u32(smem);
    const float* xin = sel_x(xp, xsel);
    const int tid = threadIdx.x, w = tid >> 5, lane = tid & 31;
    const int m = blockIdx.y;
    const int row0 = blockIdx.x * 128;
    const int kg = tid & 15;

    float* sstat = (float*)(smem + ST_OFF);
    if (tid < 128) sstat[tid] = 0.f;

    stage_B(smem, tid, layer * 9 + m);

    const float* ag = g_agg + (size_t)(m - 1) * NN * DIMN;
    for (int i = tid; i < 128 * 16; i += 256) {
        int rr = i >> 4;
        int row = row0 + rr;
        float4 v = make_float4(0.f, 0.f, 0.f, 0.f);
        if (row < NN) {
            v = *(const float4*)(xin + (size_t)row * DIMN + kg * 4);
            if (m > 0) {
                float4 a = *(const float4*)(ag + (size_t)row * DIMN + kg * 4);
                v.x += a.x; v.y += a.y; v.z += a.z; v.w += a.w;
            }
        }
        uint32_t l01, l23;
        uint32_t h01 = split2(v.x, v.y, l01), h23 = split2(v.z, v.w, l23);
        *(uint2*)(smem + AH_OFF + rr * 144 + kg * 8) = make_uint2(h01, h23);
        *(uint2*)(smem + AL_OFF + rr * 144 + kg * 8) = make_uint2(l01, l23);
    }
    __syncthreads();

    float acc[2][4][4];
#pragma unroll
    for (int a = 0; a < 2; a++)
#pragma unroll
        for (int b = 0; b < 4; b++)
#pragma unroll
            for (int c = 0; c < 4; c++) acc[a][b][c] = 0.f;

    mma_tile(sb, (w & 3) * 32, (w >> 2) * 32, lane, acc);

    __syncthreads();
    store_D(smem, lane, w, acc);
    __syncthreads();

    float* Ds = (float*)smem;
    float4 bias = make_float4(0.f, 0.f, 0.f, 0.f);
    if (m == 0) bias = *(const float4*)(bsl_l + kg * 4);
    float* outbase = (m == 0) ? g_xnew : (g_agg + (size_t)(m - 1) * NN * DIMN);
    float s[4] = {0.f, 0.f, 0.f, 0.f}, q[4] = {0.f, 0.f, 0.f, 0.f};
#pragma unroll
    for (int j = 0; j < 8; j++) {
        int rr = (tid >> 4) + j * 16;
        int row = row0 + rr;
        if (row < NN) {
            float4 v = *(float4*)(Ds + rr * 68 + kg * 4);
            if (m == 0) { v.x += bias.x; v.y += bias.y; v.z += bias.z; v.w += bias.w; }
            *(float4*)(outbase + (size_t)row * DIMN + kg * 4) = v;
            if (m > 0) {
                s[0] += v.x; s[1] += v.y; s[2] += v.z; s[3] += v.w;
                q[0] += v.x * v.x; q[1] += v.y * v.y; q[2] += v.z * v.z; q[3] += v.w * v.w;
            }
        }
    }
    if (m > 0) {
#pragma unroll
        for (int c = 0; c < 4; c++) {
            atomicAdd(&sstat[kg * 4 + c], s[c]);
            atomicAdd(&sstat[64 + kg * 4 + c], q[c]);
        }
        __syncthreads();
        if (tid < 64) {
            atomicAdd(&g_stats[(m - 1) * DIMN + tid], sstat[tid]);
            atomicAdd(&g_stats[NR * DIMN + (m - 1) * DIMN + tid], sstat[64 + tid]);
        }
    }
}

// ---------------- BN finalize ----------------
__global__ void bn_finalize_kernel(const float* __restrict__ gamma_l,
                                   const float* __restrict__ beta_l) {
    int i = threadIdx.x;   // 0..255
    float inv_n = 1.0f / (float)NN;
    float mean = g_stats[i] * inv_n;
    float var  = g_stats[NR * DIMN + i] * inv_n - mean * mean;
    float sc   = gamma_l[i] * rsqrtf(var + BN_EPS);
    g_scale[i] = sc;
    g_shift[i] = beta_l[i] - mean * sc;
}

// ---------------- gemm2: xout = relu?( xnew + sum_r relu(z_r*sc+sh)@W2_r + sum_r b2_r ) ----------------
__global__ void __launch_bounds__(256) gemm2_tc(int outsel, int do_relu, int layer,
                                                const float* __restrict__ b2_l) {
    extern __shared__ char smem[];
    uint32_t sb = smem_u32(smem);
    float* xout = (outsel == 1) ? g_xA : g_xB;
    const int tid = threadIdx.x, w = tid >> 5, lane = tid & 31;
    const int row0 = blockIdx.x * 128;
    const int kg = tid & 15;

    float acc[2][4][4];
#pragma unroll
    for (int a = 0; a < 2; a++)
#pragma unroll
        for (int b = 0; b < 4; b++)
#pragma unroll
            for (int c = 0; c < 4; c++) acc[a][b][c] = 0.f;

    for (int r = 0; r < NR; r++) {
        __syncthreads();
        stage_B(smem, tid, layer * 9 + 5 + r);
        const float* z = g_agg + (size_t)r * NN * DIMN;
        float4 sc = *(const float4*)(g_scale + r * DIMN + kg * 4);
        float4 sh = *(const float4*)(g_shift + r * DIMN + kg * 4);
        for (int i = tid; i < 128 * 16; i += 256) {
            int rr = i >> 4;
            int row = row0 + rr;
            float4 v = make_float4(0.f, 0.f, 0.f, 0.f);
            if (row < NN) {
                float4 zz = *(const float4*)(z + (size_t)row * DIMN + kg * 4);
                v.x = fmaxf(fmaf(zz.x, sc.x, sh.x), 0.f);
                v.y = fmaxf(fmaf(zz.y, sc.y, sh.y), 0.f);
                v.z = fmaxf(fmaf(zz.z, sc.z, sh.z), 0.f);
                v.w = fmaxf(fmaf(zz.w, sc.w, sh.w), 0.f);
            }
            uint32_t l01, l23;
            uint32_t h01 = split2(v.x, v.y, l01), h23 = split2(v.z, v.w, l23);
            *(uint2*)(smem + AH_OFF + rr * 144 + kg * 8) = make_uint2(h01, h23);
            *(uint2*)(smem + AL_OFF + rr * 144 + kg * 8) = make_uint2(l01, l23);
        }
        __syncthreads();
        mma_tile(sb, (w & 3) * 32, (w >> 2) * 32, lane, acc);
    }

    __syncthreads();
    store_D(smem, lane, w, acc);
    __syncthreads();

    float* Ds = (float*)smem;
    float4 b2s = make_float4(0.f, 0.f, 0.f, 0.f);
#pragma unroll
    for (int r = 0; r < NR; r++) {
        float4 b = *(const float4*)(b2_l + r * DIMN + kg * 4);
        b2s.x += b.x; b2s.y += b.y; b2s.z += b.z; b2s.w += b.w;
    }
#pragma unroll
    for (int j = 0; j < 8; j++) {
        int rr = (tid >> 4) + j * 16;
        int row = row0 + rr;
        if (row < NN) {
            float4 v = *(float4*)(Ds + rr * 68 + kg * 4);
            float4 u = *(const float4*)(g_xnew + (size_t)row * DIMN + kg * 4);
            v.x += u.x + b2s.x; v.y += u.y + b2s.y;
            v.z += u.z + b2s.z; v.w += u.w + b2s.w;
            if (do_relu) {
                v.x = fmaxf(v.x, 0.f); v.y = fmaxf(v.y, 0.f);
                v.z = fmaxf(v.z, 0.f); v.w = fmaxf(v.w, 0.f);
            }
            *(float4*)(xout + (size_t)row * DIMN + kg * 4) = v;
        }
    }
}

// ---------------- pooling ----------------
__global__ void pool_kernel(int xsel, const int* __restrict__ batch, float* __restrict__ out) {
    const float* x = sel_x(nullptr, xsel);
    int t = blockIdx.x * blockDim.x + threadIdx.x;
    int node = t >> 4;
    if (node >= NN) return;
    int lane = t & 15;
    int g = batch[node];
    float4 v = *(const float4*)(x + (size_t)node * DIMN + lane * 4);
    red_add_v4(out + g * DIMN + lane * 4, v);
    if (lane == 0) atomicAdd(&g_cnt[g], 1.0f);
}
__global__ void pool_div_kernel(float* out) {
    int i = blockIdx.x * blockDim.x + threadIdx.x;
    if (i < NG * DIMN) out[i] /= fmaxf(g_cnt[i >> 6], 1.0f);
}

// ---------------- driver ----------------
extern "C" void kernel_launch(void* const* d_in, const int* in_sizes, int n_in,
                              void* d_out, int out_size) {
    const float* x     = (const float*)d_in[0];
    const int*   ei    = (const int*)d_in[1];
    const int*   et    = (const int*)d_in[2];
    const int*   batch = (const int*)d_in[3];
    const float* Wsl   = (const float*)d_in[4];
    const float* bsl   = (const float*)d_in[5];
    const float* W1    = (const float*)d_in[6];
    /* b1 cancels under BatchNorm (mean subtraction) — unused */
    const float* gamma = (const float*)d_in[8];
    const float* beta  = (const float*)d_in[9];
    const float* W2    = (const float*)d_in[10];
    const float* b2    = (const float*)d_in[11];
    float* out = (float*)d_out;

    cudaFuncSetAttribute(gemm1_tc, cudaFuncAttributeMaxDynamicSharedMemorySize, SMEM_SZ);
    cudaFuncSetAttribute(gemm2_tc, cudaFuncAttributeMaxDynamicSharedMemorySize, SMEM_SZ);

    prep_w_kernel<<<NL * 9, 256>>>(Wsl, W1, W2);
    zero_out_kernel<<<(NG * DIMN + 255) / 256, 256>>>(out);

    // CSR build (once; graph static across layers)
    zero_cnt_kernel<<<(NN + 255) / 256, 256>>>();
    hist_kernel<<<(NE + 255) / 256, 256>>>(ei);
    scan_kernel<<<1, 1024>>>();
    fill_kernel<<<(NE + 255) / 256, 256>>>(ei, et);

    int cur = 0;  // 0 = harness input x, 1 = g_xA, 2 = g_xB
    for (int l = 0; l < NL; l++) {
        zero_stats_kernel<<<1, 512>>>();
        gather_kernel<<<(int)(((size_t)NN * 16 + 255) / 256), 256>>>(x, cur);
        gemm1_tc<<<dim3(TILES1, 5), 256, SMEM_SZ>>>(x, cur, l, bsl + (size_t)l * DIMN);
        bn_finalize_kernel<<<1, NR * DIMN>>>(gamma + (size_t)l * NR * DIMN,
                                             beta + (size_t)l * NR * DIMN);
        int nxt = (l % 2) ? 2 : 1;
        gemm2_tc<<<TILES1, 256, SMEM_SZ>>>(nxt, (l < NL - 1) ? 1 : 0, l,
                                           b2 + (size_t)l * NR * DIMN);
        cur = nxt;
    }

    pool_kernel<<<(int)(((size_t)NN * 16 + 255) / 256), 256>>>(cur, batch, out);
    pool_div_kernel<<<(NG * DIMN + 255) / 256, 256>>>(out);
}

// round 8
// speedup vs baseline: 1.9734x; 1.1283x over previous
#include <cuda_runtime.h>
#include <cuda_bf16.h>
#include <stdint.h>

#define NN 100000
#define NE 1200000
#define NR 4
#define NL 3
#define DIMN 64
#define NG 128
#define BN_EPS 1e-5f
#define TILES1 ((NN + 127) / 128)   // 782 row tiles of 128
#define NK (NN * NR)                // (node, rel) keys
#define SCAN_BLK ((NK + 4095) / 4096)

// ---------------- scratch (static device globals; no allocation) ----------------
__device__ float g_xA[(size_t)NN * DIMN];
__device__ float g_xB[(size_t)NN * DIMN];
__device__ float g_xnew[(size_t)NN * DIMN];
__device__ float g_agg[(size_t)NR * NN * DIMN];   // holds z (pre-BN) after gemm1 only
__device__ float g_stats[2 * NR * DIMN];          // [sum | sumsq]
__device__ float g_scale[NR * DIMN];
__device__ float g_shift[NR * DIMN];
__device__ float g_cnt[NG];
// CSR by (dst, rel) — built once per launch; graph static across layers
__device__ int g_ecnt[NK];
__device__ int g_ofs[NK + 1];
__device__ int g_curp[NK];
__device__ int g_bsum[128];
__device__ int g_eidx[NE];        // src node ids
// transposed + bf16-split weights: [layer][mat 0..8][n][k]; mat 0=Wsl, 1..4=W1, 5..8=W2
__device__ __align__(16) __nv_bfloat16 g_wbh[(size_t)NL * 9 * DIMN * DIMN];
__device__ __align__(16) __nv_bfloat16 g_wbl[(size_t)NL * 9 * DIMN * DIMN];

// smem layout (bytes): A rows 144B pitch (72 halves), B rows 144B pitch
#define AH_OFF 0
#define AL_OFF 18432
#define BH_OFF 36864
#define BL_OFF 46080
#define ST_OFF 55296
#define SMEM_SZ 55808

// ---------------- helpers ----------------
__device__ __forceinline__ uint32_t smem_u32(const void* p) {
    uint32_t a;
    asm("{ .reg .u64 t; cvta.to.shared.u64 t, %1; cvt.u32.u64 %0, t; }" : "=r"(a) : "l"(p));
    return a;
}
__device__ __forceinline__ void red_add_v4(float* p, float4 v) {
    asm volatile("red.global.add.v4.f32 [%0], {%1, %2, %3, %4};"
                 :: "l"(p), "f"(v.x), "f"(v.y), "f"(v.z), "f"(v.w) : "memory");
}
__device__ __forceinline__ void ldm_x4(uint32_t* r, uint32_t addr) {
    asm volatile("ldmatrix.sync.aligned.m8n8.x4.shared.b16 {%0,%1,%2,%3}, [%4];"
                 : "=r"(r[0]), "=r"(r[1]), "=r"(r[2]), "=r"(r[3]) : "r"(addr));
}
__device__ __forceinline__ void mma_bf16(float* c, const uint32_t* a, const uint32_t* b) {
    asm volatile("mma.sync.aligned.m16n8k16.row.col.f32.bf16.bf16.f32 "
                 "{%0,%1,%2,%3}, {%4,%5,%6,%7}, {%8,%9}, {%0,%1,%2,%3};"
                 : "+f"(c[0]), "+f"(c[1]), "+f"(c[2]), "+f"(c[3])
                 : "r"(a[0]), "r"(a[1]), "r"(a[2]), "r"(a[3]), "r"(b[0]), "r"(b[1]));
}
__device__ __forceinline__ uint32_t split2(float a, float b, uint32_t& lo_out) {
    __nv_bfloat16 ha = __float2bfloat16_rn(a), hb = __float2bfloat16_rn(b);
    float ra = a - __bfloat162float(ha), rb = b - __bfloat162float(hb);
    __nv_bfloat16 la = __float2bfloat16_rn(ra), lb = __float2bfloat16_rn(rb);
    lo_out = (uint32_t)__bfloat16_as_ushort(la) | ((uint32_t)__bfloat16_as_ushort(lb) << 16);
    return (uint32_t)__bfloat16_as_ushort(ha) | ((uint32_t)__bfloat16_as_ushort(hb) << 16);
}
__device__ __forceinline__ const float* sel_x(const float* p, int sel) {
    return sel == 1 ? g_xA : (sel == 2 ? g_xB : p);
}

// ---------------- weight prep ----------------
__global__ void prep_w_kernel(const float* __restrict__ Wsl, const float* __restrict__ W1,
                              const float* __restrict__ W2) {
    int b = blockIdx.x;              // 0..26 : l*9 + mat
    int l = b / 9, mm = b % 9;
    const float* src;
    if (mm == 0)      src = Wsl + (size_t)l * DIMN * DIMN;
    else if (mm <= 4) src = W1 + ((size_t)l * NR + (mm - 1)) * DIMN * DIMN;
    else              src = W2 + ((size_t)l * NR + (mm - 5)) * DIMN * DIMN;
    __nv_bfloat16* dh = g_wbh + (size_t)b * DIMN * DIMN;
    __nv_bfloat16* dl = g_wbl + (size_t)b * DIMN * DIMN;
    for (int i = threadIdx.x; i < DIMN * DIMN; i += blockDim.x) {
        int k = i >> 6, n = i & 63;
        float v = src[i];
        __nv_bfloat16 h = __float2bfloat16_rn(v);
        __nv_bfloat16 lo = __float2bfloat16_rn(v - __bfloat162float(h));
        dh[n * DIMN + k] = h;
        dl[n * DIMN + k] = lo;
    }
}

// ---------------- CSR build by (dst, rel) ----------------
__global__ void zero_cnt_kernel() {
    int i = blockIdx.x * blockDim.x + threadIdx.x;
    if (i < NK) g_ecnt[i] = 0;
}
__global__ void hist_kernel(const int* __restrict__ ei, const int* __restrict__ et) {
    int e = blockIdx.x * blockDim.x + threadIdx.x;
    if (e < NE) atomicAdd(&g_ecnt[ei[NE + e] * NR + et[e]], 1);
}
__global__ void scan_pass1() {      // per-block totals (1024 thr, 4 elems each)
    int b = blockIdx.x, tid = threadIdx.x;
    int base = b * 4096 + tid * 4;
    int s = 0;
#pragma unroll
    for (int k = 0; k < 4; k++) { int i = base + k; if (i < NK) s += g_ecnt[i]; }
    __shared__ int ws[32];
    int lane = tid & 31, wid = tid >> 5;
#pragma unroll
    for (int o = 16; o; o >>= 1) s += __shfl_down_sync(0xffffffffu, s, o);
    if (lane == 0) ws[wid] = s;
    __syncthreads();
    if (wid == 0) {
        int t = ws[lane];
#pragma unroll
        for (int o = 16; o; o >>= 1) t += __shfl_down_sync(0xffffffffu, t, o);
        if (lane == 0) g_bsum[b] = t;
    }
}
__global__ void scan_pass2() {      // single block: inclusive scan of block sums
    __shared__ int sh[128];
    int tid = threadIdx.x;
    sh[tid] = (tid < SCAN_BLK) ? g_bsum[tid] : 0;
    __syncthreads();
    for (int o = 1; o < 128; o <<= 1) {
        int t = (tid >= o) ? sh[tid - o] : 0;
        __syncthreads();
        sh[tid] += t;
        __syncthreads();
    }
    if (tid < SCAN_BLK) g_bsum[tid] = sh[tid];
    if (tid == 0) g_ofs[0] = 0;
}
__global__ void scan_pass3() {      // re-scan with global prefix; write ofs/curp
    int b = blockIdx.x, tid = threadIdx.x;
    int blockpre = b ? g_bsum[b - 1] : 0;
    int base = b * 4096 + tid * 4;
    int v[4]; int s = 0;
#pragma unroll
    for (int k = 0; k < 4; k++) { int i = base + k; v[k] = (i < NK) ? g_ecnt[i] : 0; s += v[k]; }
    int lane = tid & 31, wid = tid >> 5;
    int incl = s;
#pragma unroll
    for (int o = 1; o < 32; o <<= 1) {
        int t = __shfl_up_sync(0xffffffffu, incl, o);
        if (lane >= o) incl += t;
    }
    __shared__ int ws[32];
    if (lane == 31) ws[wid] = incl;
    __syncthreads();
    if (wid == 0) {
        int t = ws[lane];
#pragma unroll
        for (int o = 1; o < 32; o <<= 1) {
            int u = __shfl_up_sync(0xffffffffu, t, o);
            if (lane >= o) t += u;
        }
        ws[lane] = t;
    }
    __syncthreads();
    int run = blockpre + (wid ? ws[wid - 1] : 0) + (incl - s);
#pragma unroll
    for (int k = 0; k < 4; k++) {
        int i = base + k;
        if (i < NK) { g_curp[i] = run; run += v[k]; g_ofs[i + 1] = run; }
    }
}
__global__ void fill_kernel(const int* __restrict__ ei, const int* __restrict__ et) {
    int e = blockIdx.x * blockDim.x + threadIdx.x;
    if (e >= NE) return;
    int key = ei[NE + e] * NR + et[e];
    int pos = atomicAdd(&g_curp[key], 1);
    g_eidx[pos] = ei[e];
}

// ---------------- zeroing ----------------
__global__ void zero_stats_kernel() {
    int i = threadIdx.x;
    if (i < 2 * NR * DIMN) g_stats[i] = 0.f;
}
__global__ void zero_out_kernel(float* out) {
    int i = blockIdx.x * blockDim.x + threadIdx.x;
    if (i < NG * DIMN) out[i] = 0.f;
    if (i < NG) g_cnt[i] = 0.f;
}

// ---------------- shared GEMM core ----------------
__device__ __forceinline__ void mma_tile(uint32_t sb, int rowbase, int colbase, int lane,
                                         float acc[2][4][4]) {
    uint32_t aoff = (uint32_t)((lane & 15) * 144 + ((lane >> 4) << 4));
    uint32_t boff = (uint32_t)(((lane & 7) + ((lane >> 4) << 3)) * 144 + (((lane >> 3) & 1) << 4));
#pragma unroll
    for (int k = 0; k < 4; k++) {
        uint32_t kb = k * 32;
        uint32_t ah0[4], ah1[4], bh0[4], bh1[4], al0[4], al1[4], bl0[4], bl1[4];
        ldm_x4(ah0, sb + AH_OFF + rowbase * 144 + aoff + kb);
        ldm_x4(ah1, sb + AH_OFF + (rowbase + 16) * 144 + aoff + kb);
        ldm_x4(bh0, sb + BH_OFF + colbase * 144 + boff + kb);
        ldm_x4(bh1, sb + BH_OFF + (colbase + 16) * 144 + boff + kb);
        ldm_x4(al0, sb + AL_OFF + rowbase * 144 + aoff + kb);
        ldm_x4(al1, sb + AL_OFF + (rowbase + 16) * 144 + aoff + kb);
        ldm_x4(bl0, sb + BL_OFF + colbase * 144 + boff + kb);
        ldm_x4(bl1, sb + BL_OFF + (colbase + 16) * 144 + boff + kb);
#pragma unroll
        for (int nt = 0; nt < 4; nt++) {
            uint32_t* bh = (nt < 2 ? bh0 : bh1) + (nt & 1) * 2;
            uint32_t* bl = (nt < 2 ? bl0 : bl1) + (nt & 1) * 2;
            mma_bf16(acc[0][nt], ah0, bh);
            mma_bf16(acc[1][nt], ah1, bh);
            mma_bf16(acc[0][nt], ah0, bl);
            mma_bf16(acc[1][nt], ah1, bl);
            mma_bf16(acc[0][nt], al0, bh);
            mma_bf16(acc[1][nt], al1, bh);
        }
    }
}
__device__ __forceinline__ void stage_B(char* smem, int tid, int mat) {
    const char* gh = (const char*)g_wbh + (size_t)mat * 8192;
    const char* gl = (const char*)g_wbl + (size_t)mat * 8192;
    for (int i = tid; i < 64 * 8; i += 256) {
        int n = i >> 3, ch = i & 7;
        *(uint4*)(smem + BH_OFF + n * 144 + ch * 16) = *(const uint4*)(gh + n * 128 + ch * 16);
        *(uint4*)(smem + BL_OFF + n * 144 + ch * 16) = *(const uint4*)(gl + n * 128 + ch * 16);
    }
}
__device__ __forceinline__ void store_D(char* smem, int lane, int w, float acc[2][4][4]) {
    float* Ds = (float*)smem;
    int rowbase = (w & 3) * 32, colbase = (w >> 2) * 32;
    int g = lane >> 2, c2 = (lane & 3) * 2;
#pragma unroll
    for (int mt = 0; mt < 2; mt++)
#pragma unroll
        for (int nt = 0; nt < 4; nt++) {
            int row = rowbase + mt * 16 + g;
            int col = colbase + nt * 8 + c2;
            *(float2*)(Ds + row * 68 + col)       = make_float2(acc[mt][nt][0], acc[mt][nt][1]);
            *(float2*)(Ds + (row + 8) * 68 + col) = make_float2(acc[mt][nt][2], acc[mt][nt][3]);
        }
}

// ---------------- gemm1 with fused gather:
//   m=0 -> xnew = x@Wsl+bsl ; m>=1 -> z_r = (x + gatherCSR_r(x))@W1_r  (+BN stats)
__global__ void __launch_bounds__(256) gemm1_tc(const float* __restrict__ xp, int xsel,
                                                int layer, const float* __restrict__ bsl_l) {
    extern __shared__ char smem[];
    uint32_t sb = smem_u32(smem);
    const float* xin = sel_x(xp, xsel);
    const int tid = threadIdx.x, w = tid >> 5, lane = tid & 31;
    const int m = blockIdx.y;
    const int row0 = blockIdx.x * 128;
    const int kg = tid & 15;

    float* sstat = (float*)(smem + ST_OFF);
    if (tid < 128) sstat[tid] = 0.f;

    stage_B(smem, tid, layer * 9 + m);

    const int r = m - 1;
    for (int i = tid; i < 128 * 16; i += 256) {
        int rr = i >> 4;
        int row = row0 + rr;
        float4 v = make_float4(0.f, 0.f, 0.f, 0.f);
        if (row < NN) {
            v = *(const float4*)(xin + (size_t)row * DIMN + kg * 4);
            if (m > 0) {
                int key = row * NR + r;
                int beg = __ldg(&g_ofs[key]), end = __ldg(&g_ofs[key + 1]);
                for (int j = beg; j < end; j++) {
                    int s = __ldg(&g_eidx[j]);
                    float4 a = *(const float4*)(xin + (size_t)s * DIMN + kg * 4);
                    v.x += a.x; v.y += a.y; v.z += a.z; v.w += a.w;
                }
            }
        }
        uint32_t l01, l23;
        uint32_t h01 = split2(v.x, v.y, l01), h23 = split2(v.z, v.w, l23);
        *(uint2*)(smem + AH_OFF + rr * 144 + kg * 8) = make_uint2(h01, h23);
        *(uint2*)(smem + AL_OFF + rr * 144 + kg * 8) = make_uint2(l01, l23);
    }
    __syncthreads();

    float acc[2][4][4];
#pragma unroll
    for (int a = 0; a < 2; a++)
#pragma unroll
        for (int b = 0; b < 4; b++)
#pragma unroll
            for (int c = 0; c < 4; c++) acc[a][b][c] = 0.f;

    mma_tile(sb, (w & 3) * 32, (w >> 2) * 32, lane, acc);

    __syncthreads();
    store_D(smem, lane, w, acc);
    __syncthreads();

    float* Ds = (float*)smem;
    float4 bias = make_float4(0.f, 0.f, 0.f, 0.f);
    if (m == 0) bias = *(const float4*)(bsl_l + kg * 4);
    float* outbase = (m == 0) ? g_xnew : (g_agg + (size_t)r * NN * DIMN);
    float s[4] = {0.f, 0.f, 0.f, 0.f}, q[4] = {0.f, 0.f, 0.f, 0.f};
#pragma unroll
    for (int j = 0; j < 8; j++) {
        int rr = (tid >> 4) + j * 16;
        int row = row0 + rr;
        if (row < NN) {
            float4 v = *(float4*)(Ds + rr * 68 + kg * 4);
            if (m == 0) { v.x += bias.x; v.y += bias.y; v.z += bias.z; v.w += bias.w; }
            *(float4*)(outbase + (size_t)row * DIMN + kg * 4) = v;
            if (m > 0) {
                s[0] += v.x; s[1] += v.y; s[2] += v.z; s[3] += v.w;
                q[0] += v.x * v.x; q[1] += v.y * v.y; q[2] += v.z * v.z; q[3] += v.w * v.w;
            }
        }
    }
    if (m > 0) {
#pragma unroll
        for (int c = 0; c < 4; c++) {
            atomicAdd(&sstat[kg * 4 + c], s[c]);
            atomicAdd(&sstat[64 + kg * 4 + c], q[c]);
        }
        __syncthreads();
        if (tid < 64) {
            atomicAdd(&g_stats[r * DIMN + tid], sstat[tid]);
            atomicAdd(&g_stats[NR * DIMN + r * DIMN + tid], sstat[64 + tid]);
        }
    }
}

// ---------------- BN finalize ----------------
__global__ void bn_finalize_kernel(const float* __restrict__ gamma_l,
                                   const float* __restrict__ beta_l) {
    int i = threadIdx.x;   // 0..255
    float inv_n = 1.0f / (float)NN;
    float mean = g_stats[i] * inv_n;
    float var  = g_stats[NR * DIMN + i] * inv_n - mean * mean;
    float sc   = gamma_l[i] * rsqrtf(var + BN_EPS);
    g_scale[i] = sc;
    g_shift[i] = beta_l[i] - mean * sc;
}

// ---------------- gemm2: xout = relu?( xnew + sum_r relu(z_r*sc+sh)@W2_r + sum_r b2_r ) ----------------
__global__ void __launch_bounds__(256) gemm2_tc(int outsel, int do_relu, int layer,
                                                const float* __restrict__ b2_l) {
    extern __shared__ char smem[];
    uint32_t sb = smem_u32(smem);
    float* xout = (outsel == 1) ? g_xA : g_xB;
    const int tid = threadIdx.x, w = tid >> 5, lane = tid & 31;
    const int row0 = blockIdx.x * 128;
    const int kg = tid & 15;

    float acc[2][4][4];
#pragma unroll
    for (int a = 0; a < 2; a++)
#pragma unroll
        for (int b = 0; b < 4; b++)
#pragma unroll
            for (int c = 0; c < 4; c++) acc[a][b][c] = 0.f;

    for (int r = 0; r < NR; r++) {
        __syncthreads();
        stage_B(smem, tid, layer * 9 + 5 + r);
        const float* z = g_agg + (size_t)r * NN * DIMN;
        float4 sc = *(const float4*)(g_scale + r * DIMN + kg * 4);
        float4 sh = *(const float4*)(g_shift + r * DIMN + kg * 4);
        for (int i = tid; i < 128 * 16; i += 256) {
            int rr = i >> 4;
            int row = row0 + rr;
            float4 v = make_float4(0.f, 0.f, 0.f, 0.f);
            if (row < NN) {
                float4 zz = *(const float4*)(z + (size_t)row * DIMN + kg * 4);
                v.x = fmaxf(fmaf(zz.x, sc.x, sh.x), 0.f);
                v.y = fmaxf(fmaf(zz.y, sc.y, sh.y), 0.f);
                v.z = fmaxf(fmaf(zz.z, sc.z, sh.z), 0.f);
                v.w = fmaxf(fmaf(zz.w, sc.w, sh.w), 0.f);
            }
            uint32_t l01, l23;
            uint32_t h01 = split2(v.x, v.y, l01), h23 = split2(v.z, v.w, l23);
            *(uint2*)(smem + AH_OFF + rr * 144 + kg * 8) = make_uint2(h01, h23);
            *(uint2*)(smem + AL_OFF + rr * 144 + kg * 8) = make_uint2(l01, l23);
        }
        __syncthreads();
        mma_tile(sb, (w & 3) * 32, (w >> 2) * 32, lane, acc);
    }

    __syncthreads();
    store_D(smem, lane, w, acc);
    __syncthreads();

    float* Ds = (float*)smem;
    float4 b2s = make_float4(0.f, 0.f, 0.f, 0.f);
#pragma unroll
    for (int r = 0; r < NR; r++) {
        float4 b = *(const float4*)(b2_l + r * DIMN + kg * 4);
        b2s.x += b.x; b2s.y += b.y; b2s.z += b.z; b2s.w += b.w;
    }
#pragma unroll
    for (int j = 0; j < 8; j++) {
        int rr = (tid >> 4) + j * 16;
        int row = row0 + rr;
        if (row < NN) {
            float4 v = *(float4*)(Ds + rr * 68 + kg * 4);
            float4 u = *(const float4*)(g_xnew + (size_t)row * DIMN + kg * 4);
            v.x += u.x + b2s.x; v.y += u.y + b2s.y;
            v.z += u.z + b2s.z; v.w += u.w + b2s.w;
            if (do_relu) {
                v.x = fmaxf(v.x, 0.f); v.y = fmaxf(v.y, 0.f);
                v.z = fmaxf(v.z, 0.f); v.w = fmaxf(v.w, 0.f);
            }
            *(float4*)(xout + (size_t)row * DIMN + kg * 4) = v;
        }
    }
}

// ---------------- pooling ----------------
__global__ void pool_kernel(int xsel, const int* __restrict__ batch, float* __restrict__ out) {
    const float* x = sel_x(nullptr, xsel);
    int t = blockIdx.x * blockDim.x + threadIdx.x;
    int node = t >> 4;
    if (node >= NN) return;
    int lane = t & 15;
    int g = batch[node];
    float4 v = *(const float4*)(x + (size_t)node * DIMN + lane * 4);
    red_add_v4(out + g * DIMN + lane * 4, v);
    if (lane == 0) atomicAdd(&g_cnt[g], 1.0f);
}
__global__ void pool_div_kernel(float* out) {
    int i = blockIdx.x * blockDim.x + threadIdx.x;
    if (i < NG * DIMN) out[i] /= fmaxf(g_cnt[i >> 6], 1.0f);
}

// ---------------- driver ----------------
extern "C" void kernel_launch(void* const* d_in, const int* in_sizes, int n_in,
                              void* d_out, int out_size) {
    const float* x     = (const float*)d_in[0];
    const int*   ei    = (const int*)d_in[1];
    const int*   et    = (const int*)d_in[2];
    const int*   batch = (const int*)d_in[3];
    const float* Wsl   = (const float*)d_in[4];
    const float* bsl   = (const float*)d_in[5];
    const float* W1    = (const float*)d_in[6];
    /* b1 cancels under BatchNorm (mean subtraction) — unused */
    const float* gamma = (const float*)d_in[8];
    const float* beta  = (const float*)d_in[9];
    const float* W2    = (const float*)d_in[10];
    const float* b2    = (const float*)d_in[11];
    float* out = (float*)d_out;

    cudaFuncSetAttribute(gemm1_tc, cudaFuncAttributeMaxDynamicSharedMemorySize, SMEM_SZ);
    cudaFuncSetAttribute(gemm2_tc, cudaFuncAttributeMaxDynamicSharedMemorySize, SMEM_SZ);

    prep_w_kernel<<<NL * 9, 256>>>(Wsl, W1, W2);
    zero_out_kernel<<<(NG * DIMN + 255) / 256, 256>>>(out);

    // CSR build by (dst, rel) — once; graph static across layers
    zero_cnt_kernel<<<(NK + 255) / 256, 256>>>();
    hist_kernel<<<(NE + 255) / 256, 256>>>(ei, et);
    scan_pass1<<<SCAN_BLK, 1024>>>();
    scan_pass2<<<1, 128>>>();
    scan_pass3<<<SCAN_BLK, 1024>>>();
    fill_kernel<<<(NE + 255) / 256, 256>>>(ei, et);

    int cur = 0;  // 0 = harness input x, 1 = g_xA, 2 = g_xB
    for (int l = 0; l < NL; l++) {
        zero_stats_kernel<<<1, 512>>>();
        gemm1_tc<<<dim3(TILES1, 5), 256, SMEM_SZ>>>(x, cur, l, bsl + (size_t)l * DIMN);
        bn_finalize_kernel<<<1, NR * DIMN>>>(gamma + (size_t)l * NR * DIMN,
                                             beta + (size_t)l * NR * DIMN);
        int nxt = (l % 2) ? 2 : 1;
        gemm2_tc<<<TILES1, 256, SMEM_SZ>>>(nxt, (l < NL - 1) ? 1 : 0, l,
                                           b2 + (size_t)l * NR * DIMN);
        cur = nxt;
    }

    pool_kernel<<<(int)(((size_t)NN * 16 + 255) / 256), 256>>>(cur, batch, out);
    pool_div_kernel<<<(NG * DIMN + 255) / 256, 256>>>(out);
}

// round 9
// speedup vs baseline: 2.1139x; 1.0712x over previous
#include <cuda_runtime.h>
#include <cuda_bf16.h>
#include <stdint.h>

#define NN 100000
#define NE 1200000
#define NR 4
#define NL 3
#define DIMN 64
#define NG 128
#define BN_EPS 1e-5f
#define TILES1 ((NN + 127) / 128)   // 782 row tiles of 128
#define NK (NN * NR)                // (node, rel) keys
#define SCAN_BLK ((NK + 4095) / 4096)

// ---------------- scratch (static device globals; no allocation) ----------------
__device__ float g_xA[(size_t)NN * DIMN];
__device__ float g_xB[(size_t)NN * DIMN];
__device__ float g_xnew[(size_t)NN * DIMN];
__device__ float g_agg[(size_t)NR * NN * DIMN];   // holds z (pre-BN) after gemm1 only
__device__ float g_stats[2 * NR * DIMN];          // [sum | sumsq]
__device__ float g_scale[NR * DIMN];
__device__ float g_shift[NR * DIMN];
__device__ float g_cnt[NG];
// CSR by (dst, rel) — built once per launch; graph static across layers
__device__ int g_ecnt[NK];
__device__ int g_ofs[NK + 1];
__device__ int g_curp[NK];
__device__ int g_bsum[128];
__device__ int g_eidx[NE];        // src node ids
// transposed + bf16-split weights: [layer][mat 0..8][n][k]; mat 0=Wsl, 1..4=W1, 5..8=W2
__device__ __align__(16) __nv_bfloat16 g_wbh[(size_t)NL * 9 * DIMN * DIMN];
__device__ __align__(16) __nv_bfloat16 g_wbl[(size_t)NL * 9 * DIMN * DIMN];

// smem layout (bytes): A rows 144B pitch (72 halves), B rows 144B pitch
#define AH_OFF 0
#define AL_OFF 18432
#define BH_OFF 36864
#define BL_OFF 46080
#define ST_OFF 55296
#define SMEM_SZ 55808

// ---------------- helpers ----------------
__device__ __forceinline__ uint32_t smem_u32(const void* p) {
    uint32_t a;
    asm("{ .reg .u64 t; cvta.to.shared.u64 t, %1; cvt.u32.u64 %0, t; }" : "=r"(a) : "l"(p));
    return a;
}
__device__ __forceinline__ void red_add_v4(float* p, float4 v) {
    asm volatile("red.global.add.v4.f32 [%0], {%1, %2, %3, %4};"
                 :: "l"(p), "f"(v.x), "f"(v.y), "f"(v.z), "f"(v.w) : "memory");
}
__device__ __forceinline__ void ldm_x4(uint32_t* r, uint32_t addr) {
    asm volatile("ldmatrix.sync.aligned.m8n8.x4.shared.b16 {%0,%1,%2,%3}, [%4];"
                 : "=r"(r[0]), "=r"(r[1]), "=r"(r[2]), "=r"(r[3]) : "r"(addr));
}
__device__ __forceinline__ void mma_bf16(float* c, const uint32_t* a, const uint32_t* b) {
    asm volatile("mma.sync.aligned.m16n8k16.row.col.f32.bf16.bf16.f32 "
                 "{%0,%1,%2,%3}, {%4,%5,%6,%7}, {%8,%9}, {%0,%1,%2,%3};"
                 : "+f"(c[0]), "+f"(c[1]), "+f"(c[2]), "+f"(c[3])
                 : "r"(a[0]), "r"(a[1]), "r"(a[2]), "r"(a[3]), "r"(b[0]), "r"(b[1]));
}
__device__ __forceinline__ uint32_t split2(float a, float b, uint32_t& lo_out) {
    __nv_bfloat16 ha = __float2bfloat16_rn(a), hb = __float2bfloat16_rn(b);
    float ra = a - __bfloat162float(ha), rb = b - __bfloat162float(hb);
    __nv_bfloat16 la = __float2bfloat16_rn(ra), lb = __float2bfloat16_rn(rb);
    lo_out = (uint32_t)__bfloat16_as_ushort(la) | ((uint32_t)__bfloat16_as_ushort(lb) << 16);
    return (uint32_t)__bfloat16_as_ushort(ha) | ((uint32_t)__bfloat16_as_ushort(hb) << 16);
}
__device__ __forceinline__ const float* sel_x(const float* p, int sel) {
    return sel == 1 ? g_xA : (sel == 2 ? g_xB : p);
}

// ---------------- weight prep ----------------
__global__ void prep_w_kernel(const float* __restrict__ Wsl, const float* __restrict__ W1,
                              const float* __restrict__ W2) {
    int b = blockIdx.x;              // 0..26 : l*9 + mat
    int l = b / 9, mm = b % 9;
    const float* src;
    if (mm == 0)      src = Wsl + (size_t)l * DIMN * DIMN;
    else if (mm <= 4) src = W1 + ((size_t)l * NR + (mm - 1)) * DIMN * DIMN;
    else              src = W2 + ((size_t)l * NR + (mm - 5)) * DIMN * DIMN;
    __nv_bfloat16* dh = g_wbh + (size_t)b * DIMN * DIMN;
    __nv_bfloat16* dl = g_wbl + (size_t)b * DIMN * DIMN;
    for (int i = threadIdx.x; i < DIMN * DIMN; i += blockDim.x) {
        int k = i >> 6, n = i & 63;
        float v = src[i];
        __nv_bfloat16 h = __float2bfloat16_rn(v);
        __nv_bfloat16 lo = __float2bfloat16_rn(v - __bfloat162float(h));
        dh[n * DIMN + k] = h;
        dl[n * DIMN + k] = lo;
    }
}

// ---------------- combined init: out, g_cnt, g_ecnt, g_stats ----------------
__global__ void init_kernel(float* out) {
    int i = blockIdx.x * blockDim.x + threadIdx.x;
    if (i < NK) g_ecnt[i] = 0;
    if (i < NG * DIMN) out[i] = 0.f;
    if (i < NG) g_cnt[i] = 0.f;
    if (i < 2 * NR * DIMN) g_stats[i] = 0.f;
}

// ---------------- CSR build by (dst, rel) ----------------
__global__ void hist_kernel(const int* __restrict__ ei, const int* __restrict__ et) {
    int e = blockIdx.x * blockDim.x + threadIdx.x;
    if (e < NE) atomicAdd(&g_ecnt[ei[NE + e] * NR + et[e]], 1);
}
__global__ void scan_pass1() {      // per-block totals (1024 thr, 4 elems each)
    int b = blockIdx.x, tid = threadIdx.x;
    int base = b * 4096 + tid * 4;
    int s = 0;
#pragma unroll
    for (int k = 0; k < 4; k++) { int i = base + k; if (i < NK) s += g_ecnt[i]; }
    __shared__ int ws[32];
    int lane = tid & 31, wid = tid >> 5;
#pragma unroll
    for (int o = 16; o; o >>= 1) s += __shfl_down_sync(0xffffffffu, s, o);
    if (lane == 0) ws[wid] = s;
    __syncthreads();
    if (wid == 0) {
        int t = ws[lane];
#pragma unroll
        for (int o = 16; o; o >>= 1) t += __shfl_down_sync(0xffffffffu, t, o);
        if (lane == 0) g_bsum[b] = t;
    }
}
__global__ void scan_pass2() {      // single block: inclusive scan of block sums
    __shared__ int sh[128];
    int tid = threadIdx.x;
    sh[tid] = (tid < SCAN_BLK) ? g_bsum[tid] : 0;
    __syncthreads();
    for (int o = 1; o < 128; o <<= 1) {
        int t = (tid >= o) ? sh[tid - o] : 0;
        __syncthreads();
        sh[tid] += t;
        __syncthreads();
    }
    if (tid < SCAN_BLK) g_bsum[tid] = sh[tid];
    if (tid == 0) g_ofs[0] = 0;
}
__global__ void scan_pass3() {      // re-scan with global prefix; write ofs/curp
    int b = blockIdx.x, tid = threadIdx.x;
    int blockpre = b ? g_bsum[b - 1] : 0;
    int base = b * 4096 + tid * 4;
    int v[4]; int s = 0;
#pragma unroll
    for (int k = 0; k < 4; k++) { int i = base + k; v[k] = (i < NK) ? g_ecnt[i] : 0; s += v[k]; }
    int lane = tid & 31, wid = tid >> 5;
    int incl = s;
#pragma unroll
    for (int o = 1; o < 32; o <<= 1) {
        int t = __shfl_up_sync(0xffffffffu, incl, o);
        if (lane >= o) incl += t;
    }
    __shared__ int ws[32];
    if (lane == 31) ws[wid] = incl;
    __syncthreads();
    if (wid == 0) {
        int t = ws[lane];
#pragma unroll
        for (int o = 1; o < 32; o <<= 1) {
            int u = __shfl_up_sync(0xffffffffu, t, o);
            if (lane >= o) t += u;
        }
        ws[lane] = t;
    }
    __syncthreads();
    int run = blockpre + (wid ? ws[wid - 1] : 0) + (incl - s);
#pragma unroll
    for (int k = 0; k < 4; k++) {
        int i = base + k;
        if (i < NK) { g_curp[i] = run; run += v[k]; g_ofs[i + 1] = run; }
    }
}
__global__ void fill_kernel(const int* __restrict__ ei, const int* __restrict__ et) {
    int e = blockIdx.x * blockDim.x + threadIdx.x;
    if (e >= NE) return;
    int key = ei[NE + e] * NR + et[e];
    int pos = atomicAdd(&g_curp[key], 1);
    g_eidx[pos] = ei[e];
}

// ---------------- shared GEMM core ----------------
__device__ __forceinline__ void mma_tile(uint32_t sb, int rowbase, int colbase, int lane,
                                         float acc[2][4][4]) {
    uint32_t aoff = (uint32_t)((lane & 15) * 144 + ((lane >> 4) << 4));
    uint32_t boff = (uint32_t)(((lane & 7) + ((lane >> 4) << 3)) * 144 + (((lane >> 3) & 1) << 4));
#pragma unroll
    for (int k = 0; k < 4; k++) {
        uint32_t kb = k * 32;
        uint32_t ah0[4], ah1[4], bh0[4], bh1[4], al0[4], al1[4], bl0[4], bl1[4];
        ldm_x4(ah0, sb + AH_OFF + rowbase * 144 + aoff + kb);
        ldm_x4(ah1, sb + AH_OFF + (rowbase + 16) * 144 + aoff + kb);
        ldm_x4(bh0, sb + BH_OFF + colbase * 144 + boff + kb);
        ldm_x4(bh1, sb + BH_OFF + (colbase + 16) * 144 + boff + kb);
        ldm_x4(al0, sb + AL_OFF + rowbase * 144 + aoff + kb);
        ldm_x4(al1, sb + AL_OFF + (rowbase + 16) * 144 + aoff + kb);
        ldm_x4(bl0, sb + BL_OFF + colbase * 144 + boff + kb);
        ldm_x4(bl1, sb + BL_OFF + (colbase + 16) * 144 + boff + kb);
#pragma unroll
        for (int nt = 0; nt < 4; nt++) {
            uint32_t* bh = (nt < 2 ? bh0 : bh1) + (nt & 1) * 2;
            uint32_t* bl = (nt < 2 ? bl0 : bl1) + (nt & 1) * 2;
            mma_bf16(acc[0][nt], ah0, bh);
            mma_bf16(acc[1][nt], ah1, bh);
            mma_bf16(acc[0][nt], ah0, bl);
            mma_bf16(acc[1][nt], ah1, bl);
            mma_bf16(acc[0][nt], al0, bh);
            mma_bf16(acc[1][nt], al1, bh);
        }
    }
}
__device__ __forceinline__ void stage_B(char* smem, int tid, int mat) {
    const char* gh = (const char*)g_wbh + (size_t)mat * 8192;
    const char* gl = (const char*)g_wbl + (size_t)mat * 8192;
    for (int i = tid; i < 64 * 8; i += 256) {
        int n = i >> 3, ch = i & 7;
        *(uint4*)(smem + BH_OFF + n * 144 + ch * 16) = *(const uint4*)(gh + n * 128 + ch * 16);
        *(uint4*)(smem + BL_OFF + n * 144 + ch * 16) = *(const uint4*)(gl + n * 128 + ch * 16);
    }
}
__device__ __forceinline__ void store_D(char* smem, int lane, int w, float acc[2][4][4]) {
    float* Ds = (float*)smem;
    int rowbase = (w & 3) * 32, colbase = (w >> 2) * 32;
    int g = lane >> 2, c2 = (lane & 3) * 2;
#pragma unroll
    for (int mt = 0; mt < 2; mt++)
#pragma unroll
        for (int nt = 0; nt < 4; nt++) {
            int row = rowbase + mt * 16 + g;
            int col = colbase + nt * 8 + c2;
            *(float2*)(Ds + row * 68 + col)       = make_float2(acc[mt][nt][0], acc[mt][nt][1]);
            *(float2*)(Ds + (row + 8) * 68 + col) = make_float2(acc[mt][nt][2], acc[mt][nt][3]);
        }
}

// ---------------- gemm1 with fused gather (batched edge prefetch):
//   m=0 -> xnew = x@Wsl+bsl ; m>=1 -> z_r = (x + gatherCSR_r(x))@W1_r  (+BN stats)
__global__ void __launch_bounds__(256) gemm1_tc(const float* __restrict__ xp, int xsel,
                                                int layer, const float* __restrict__ bsl_l) {
    extern __shared__ char smem[];
    uint32_t sb = smem_u32(smem);
    const float* xin = sel_x(xp, xsel);
    const int tid = threadIdx.x, w = tid >> 5, lane = tid & 31;
    const int m = blockIdx.y;
    const int row0 = blockIdx.x * 128;
    const int kg = tid & 15;

    float* sstat = (float*)(smem + ST_OFF);
    if (tid < 128) sstat[tid] = 0.f;

    stage_B(smem, tid, layer * 9 + m);

    const int r = m - 1;
#pragma unroll 2
    for (int i = tid; i < 128 * 16; i += 256) {
        int rr = i >> 4;
        int row = row0 + rr;
        float4 v = make_float4(0.f, 0.f, 0.f, 0.f);
        if (row < NN) {
            v = *(const float4*)(xin + (size_t)row * DIMN + kg * 4);
            if (m > 0) {
                int key = row * NR + r;
                int beg = __ldg(&g_ofs[key]);
                int cnt = __ldg(&g_ofs[key + 1]) - beg;
                int pre = cnt < 8 ? cnt : 8;
                int sidx[8];
#pragma unroll
                for (int t = 0; t < 8; t++)
                    if (t < pre) sidx[t] = __ldg(&g_eidx[beg + t]);
#pragma unroll
                for (int t = 0; t < 8; t++) {
                    if (t < pre) {
                        float4 a = *(const float4*)(xin + (size_t)sidx[t] * DIMN + kg * 4);
                        v.x += a.x; v.y += a.y; v.z += a.z; v.w += a.w;
                    }
                }
                for (int t = 8; t < cnt; t++) {
                    int s = __ldg(&g_eidx[beg + t]);
                    float4 a = *(const float4*)(xin + (size_t)s * DIMN + kg * 4);
                    v.x += a.x; v.y += a.y; v.z += a.z; v.w += a.w;
                }
            }
        }
        uint32_t l01, l23;
        uint32_t h01 = split2(v.x, v.y, l01), h23 = split2(v.z, v.w, l23);
        *(uint2*)(smem + AH_OFF + rr * 144 + kg * 8) = make_uint2(h01, h23);
        *(uint2*)(smem + AL_OFF + rr * 144 + kg * 8) = make_uint2(l01, l23);
    }
    __syncthreads();

    float acc[2][4][4];
#pragma unroll
    for (int a = 0; a < 2; a++)
#pragma unroll
        for (int b = 0; b < 4; b++)
#pragma unroll
            for (int c = 0; c < 4; c++) acc[a][b][c] = 0.f;

    mma_tile(sb, (w & 3) * 32, (w >> 2) * 32, lane, acc);

    __syncthreads();
    store_D(smem, lane, w, acc);
    __syncthreads();

    float* Ds = (float*)smem;
    float4 bias = make_float4(0.f, 0.f, 0.f, 0.f);
    if (m == 0) bias = *(const float4*)(bsl_l + kg * 4);
    float* outbase = (m == 0) ? g_xnew : (g_agg + (size_t)r * NN * DIMN);
    float s[4] = {0.f, 0.f, 0.f, 0.f}, q[4] = {0.f, 0.f, 0.f, 0.f};
#pragma unroll
    for (int j = 0; j < 8; j++) {
        int rr = (tid >> 4) + j * 16;
        int row = row0 + rr;
        if (row < NN) {
            float4 v = *(float4*)(Ds + rr * 68 + kg * 4);
            if (m == 0) { v.x += bias.x; v.y += bias.y; v.z += bias.z; v.w += bias.w; }
            *(float4*)(outbase + (size_t)row * DIMN + kg * 4) = v;
            if (m > 0) {
                s[0] += v.x; s[1] += v.y; s[2] += v.z; s[3] += v.w;
                q[0] += v.x * v.x; q[1] += v.y * v.y; q[2] += v.z * v.z; q[3] += v.w * v.w;
            }
        }
    }
    if (m > 0) {
#pragma unroll
        for (int c = 0; c < 4; c++) {
            atomicAdd(&sstat[kg * 4 + c], s[c]);
            atomicAdd(&sstat[64 + kg * 4 + c], q[c]);
        }
        __syncthreads();
        if (tid < 64) {
            atomicAdd(&g_stats[r * DIMN + tid], sstat[tid]);
            atomicAdd(&g_stats[NR * DIMN + r * DIMN + tid], sstat[64 + tid]);
        }
    }
}

// ---------------- BN finalize (self-zeroes stats for the next layer) ----------------
__global__ void bn_finalize_kernel(const float* __restrict__ gamma_l,
                                   const float* __restrict__ beta_l) {
    int i = threadIdx.x;   // 0..255
    float inv_n = 1.0f / (float)NN;
    float sum = g_stats[i], sumsq = g_stats[NR * DIMN + i];
    float mean = sum * inv_n;
    float var  = sumsq * inv_n - mean * mean;
    float sc   = gamma_l[i] * rsqrtf(var + BN_EPS);
    g_scale[i] = sc;
    g_shift[i] = beta_l[i] - mean * sc;
    g_stats[i] = 0.f;
    g_stats[NR * DIMN + i] = 0.f;
}

// ---------------- gemm2: xout = relu?( xnew + sum_r relu(z_r*sc+sh)@W2_r + sum_r b2_r ) ----------------
__global__ void __launch_bounds__(256) gemm2_tc(int outsel, int do_relu, int layer,
                                                const float* __restrict__ b2_l) {
    extern __shared__ char smem[];
    uint32_t sb = smem_u32(smem);
    float* xout = (outsel == 1) ? g_xA : g_xB;
    const int tid = threadIdx.x, w = tid >> 5, lane = tid & 31;
    const int row0 = blockIdx.x * 128;
    const int kg = tid & 15;

    float acc[2][4][4];
#pragma unroll
    for (int a = 0; a < 2; a++)
#pragma unroll
        for (int b = 0; b < 4; b++)
#pragma unroll
            for (int c = 0; c < 4; c++) acc[a][b][c] = 0.f;

    for (int r = 0; r < NR; r++) {
        __syncthreads();
        stage_B(smem, tid, layer * 9 + 5 + r);
        const float* z = g_agg + (size_t)r * NN * DIMN;
        float4 sc = *(const float4*)(g_scale + r * DIMN + kg * 4);
        float4 sh = *(const float4*)(g_shift + r * DIMN + kg * 4);
        for (int i = tid; i < 128 * 16; i += 256) {
            int rr = i >> 4;
            int row = row0 + rr;
            float4 v = make_float4(0.f, 0.f, 0.f, 0.f);
            if (row < NN) {
                float4 zz = *(const float4*)(z + (size_t)row * DIMN + kg * 4);
                v.x = fmaxf(fmaf(zz.x, sc.x, sh.x), 0.f);
                v.y = fmaxf(fmaf(zz.y, sc.y, sh.y), 0.f);
                v.z = fmaxf(fmaf(zz.z, sc.z, sh.z), 0.f);
                v.w = fmaxf(fmaf(zz.w, sc.w, sh.w), 0.f);
            }
            uint32_t l01, l23;
            uint32_t h01 = split2(v.x, v.y, l01), h23 = split2(v.z, v.w, l23);
            *(uint2*)(smem + AH_OFF + rr * 144 + kg * 8) = make_uint2(h01, h23);
            *(uint2*)(smem + AL_OFF + rr * 144 + kg * 8) = make_uint2(l01, l23);
        }
        __syncthreads();
        mma_tile(sb, (w & 3) * 32, (w >> 2) * 32, lane, acc);
    }

    __syncthreads();
    store_D(smem, lane, w, acc);
    __syncthreads();

    float* Ds = (float*)smem;
    float4 b2s = make_float4(0.f, 0.f, 0.f, 0.f);
#pragma unroll
    for (int r = 0; r < NR; r++) {
        float4 b = *(const float4*)(b2_l + r * DIMN + kg * 4);
        b2s.x += b.x; b2s.y += b.y; b2s.z += b.z; b2s.w += b.w;
    }
#pragma unroll
    for (int j = 0; j < 8; j++) {
        int rr = (tid >> 4) + j * 16;
        int row = row0 + rr;
        if (row < NN) {
            float4 v = *(float4*)(Ds + rr * 68 + kg * 4);
            float4 u = *(const float4*)(g_xnew + (size_t)row * DIMN + kg * 4);
            v.x += u.x + b2s.x; v.y += u.y + b2s.y;
            v.z += u.z + b2s.z; v.w += u.w + b2s.w;
            if (do_relu) {
                v.x = fmaxf(v.x, 0.f); v.y = fmaxf(v.y, 0.f);
                v.z = fmaxf(v.z, 0.f); v.w = fmaxf(v.w, 0.f);
            }
            *(float4*)(xout + (size_t)row * DIMN + kg * 4) = v;
        }
    }
}

// ---------------- pooling ----------------
__global__ void pool_kernel(int xsel, const int* __restrict__ batch, float* __restrict__ out) {
    const float* x = sel_x(nullptr, xsel);
    int t = blockIdx.x * blockDim.x + threadIdx.x;
    int node = t >> 4;
    if (node >= NN) return;
    int lane = t & 15;
    int g = batch[node];
    float4 v = *(const float4*)(x + (size_t)node * DIMN + lane * 4);
    red_add_v4(out + g * DIMN + lane * 4, v);
    if (lane == 0) atomicAdd(&g_cnt[g], 1.0f);
}
__global__ void pool_div_kernel(float* out) {
    int i = blockIdx.x * blockDim.x + threadIdx.x;
    if (i < NG * DIMN) out[i] /= fmaxf(g_cnt[i >> 6], 1.0f);
}

// ---------------- driver ----------------
extern "C" void kernel_launch(void* const* d_in, const int* in_sizes, int n_in,
                              void* d_out, int out_size) {
    const float* x     = (const float*)d_in[0];
    const int*   ei    = (const int*)d_in[1];
    const int*   et    = (const int*)d_in[2];
    const int*   batch = (const int*)d_in[3];
    const float* Wsl   = (const float*)d_in[4];
    const float* bsl   = (const float*)d_in[5];
    const float* W1    = (const float*)d_in[6];
    /* b1 cancels under BatchNorm (mean subtraction) — unused */
    const float* gamma = (const float*)d_in[8];
    const float* beta  = (const float*)d_in[9];
    const float* W2    = (const float*)d_in[10];
    const float* b2    = (const float*)d_in[11];
    float* out = (float*)d_out;

    cudaFuncSetAttribute(gemm1_tc, cudaFuncAttributeMaxDynamicSharedMemorySize, SMEM_SZ);
    cudaFuncSetAttribute(gemm2_tc, cudaFuncAttributeMaxDynamicSharedMemorySize, SMEM_SZ);

    prep_w_kernel<<<NL * 9, 256>>>(Wsl, W1, W2);
    init_kernel<<<(NK + 255) / 256, 256>>>(out);

    // CSR build by (dst, rel) — once; graph static across layers
    hist_kernel<<<(NE + 255) / 256, 256>>>(ei, et);
    scan_pass1<<<SCAN_BLK, 1024>>>();
    scan_pass2<<<1, 128>>>();
    scan_pass3<<<SCAN_BLK, 1024>>>();
    fill_kernel<<<(NE + 255) / 256, 256>>>(ei, et);

    int cur = 0;  // 0 = harness input x, 1 = g_xA, 2 = g_xB
    for (int l = 0; l < NL; l++) {
        gemm1_tc<<<dim3(TILES1, 5), 256, SMEM_SZ>>>(x, cur, l, bsl + (size_t)l * DIMN);
        bn_finalize_kernel<<<1, NR * DIMN>>>(gamma + (size_t)l * NR * DIMN,
                                             beta + (size_t)l * NR * DIMN);
        int nxt = (l % 2) ? 2 : 1;
        gemm2_tc<<<TILES1, 256, SMEM_SZ>>>(nxt, (l < NL - 1) ? 1 : 0, l,
                                           b2 + (size_t)l * NR * DIMN);
        cur = nxt;
    }

    pool_kernel<<<(int)(((size_t)NN * 16 + 255) / 256), 256>>>(cur, batch, out);
    pool_div_kernel<<<(NG * DIMN + 255) / 256, 256>>>(out);
}